// round 7
// baseline (speedup 1.0000x reference)
#include <cuda_runtime.h>
#include <cuda_bf16.h>
#include <cuda_fp8.h>
#include <stdint.h>

// ---------------- problem constants ----------------
static constexpr int B_    = 16384;
static constexpr int KX    = 384;   // padded input K in fp8 (288 -> 384, 3 chunks of 128)
static constexpr int KH    = 640;   // padded hidden K (512 + 32 z + pad -> 5 chunks of 128)
static constexpr int H     = 512;
static constexpr int M_OUT = 128;
static constexpr int NE    = 8;
static constexpr int NS    = NE + 1; // 8 experts + gate slot
static constexpr float WSCALE  = 32.f;   // weight scale into e4m3
static constexpr float IWSCALE = 1.f / 32.f;

// ---------------- scratch layout (single __device__ array, bytes) ----------------
static constexpr size_t OFF_XPAD = 0;
static constexpr size_t SZ_XPAD  = (size_t)B_*KX;            // fp8
static constexpr size_t OFF_H1   = OFF_XPAD + SZ_XPAD;
static constexpr size_t SZ_HEXT  = (size_t)NS*B_*KH;         // fp8, 9 slots (slot 8 = gate)
static constexpr size_t OFF_H2   = OFF_H1 + SZ_HEXT;
static constexpr size_t OFF_H3   = OFF_H2 + SZ_HEXT;
static constexpr size_t SZ_H3    = (size_t)NE*B_*M_OUT*2;    // bf16
static constexpr size_t OFF_PARA = OFF_H3 + SZ_H3;
static constexpr size_t SZ_PARA  = (size_t)B_*NE*4;
static constexpr size_t OFF_PART = OFF_PARA + SZ_PARA;
static constexpr size_t SZ_PART  = 2048*4;
static constexpr size_t OFF_INV  = OFF_PART + SZ_PART;
static constexpr size_t SZ_INV   = 256;
static constexpr size_t OFF_W1T  = OFF_INV + SZ_INV;
static constexpr size_t SZ_W1T   = (size_t)NS*H*KX;          // fp8
static constexpr size_t OFF_W2T  = OFF_W1T + SZ_W1T;
static constexpr size_t SZ_W2T   = (size_t)NS*H*KH;
static constexpr size_t OFF_W3T  = OFF_W2T + SZ_W2T;
static constexpr size_t SZ_W3T   = (size_t)NE*M_OUT*KH;
static constexpr size_t OFF_B1A  = OFF_W3T + SZ_W3T;
static constexpr size_t SZ_B1A   = (size_t)NS*H*4;
static constexpr size_t OFF_B2A  = OFF_B1A + SZ_B1A;
static constexpr size_t SZ_B2A   = (size_t)NS*H*4;
static constexpr size_t SCRATCH_TOTAL = OFF_B2A + SZ_B2A;

__device__ __align__(1024) unsigned char g_scratch[SCRATCH_TOTAL];

// ---------------- helpers ----------------
__device__ __forceinline__ uint32_t smem_u32(const void* p) {
    return (uint32_t)__cvta_generic_to_shared(p);
}
__device__ __forceinline__ uint32_t swz128(uint32_t off) {
    return off ^ ((off >> 3) & 0x70);
}
__device__ __forceinline__ void cp16(uint32_t dst, const void* src) {
    asm volatile("cp.async.cg.shared.global [%0], [%1], 16;\n" :: "r"(dst), "l"(src) : "memory");
}
__device__ __forceinline__ void ldsm_x4(uint32_t& r0, uint32_t& r1, uint32_t& r2, uint32_t& r3,
                                        uint32_t addr) {
    asm volatile("ldmatrix.sync.aligned.m8n8.x4.shared.b16 {%0,%1,%2,%3}, [%4];"
                 : "=r"(r0), "=r"(r1), "=r"(r2), "=r"(r3) : "r"(addr));
}
// fp8 e4m3 MMA, K=32, f32 accum. Byte-level fragment layout matches bf16 k16
// (every b16 lane-pair becomes a 4-byte fp8 quad), so ldmatrix.b16 addressing is reused.
__device__ __forceinline__ void mma16832(float* c, uint32_t a0, uint32_t a1, uint32_t a2, uint32_t a3,
                                         uint32_t b0, uint32_t b1) {
    asm volatile(
        "mma.sync.aligned.m16n8k32.row.col.f32.e4m3.e4m3.f32 "
        "{%0,%1,%2,%3}, {%4,%5,%6,%7}, {%8,%9}, {%0,%1,%2,%3};"
        : "+f"(c[0]), "+f"(c[1]), "+f"(c[2]), "+f"(c[3])
        : "r"(a0), "r"(a1), "r"(a2), "r"(a3), "r"(b0), "r"(b1));
}
__device__ __forceinline__ uint8_t to_fp8(float v) {
    return (uint8_t)__nv_cvt_float_to_fp8(v, __NV_SATFINITE, __NV_E4M3);
}
__device__ __forceinline__ float from_fp8(uint8_t b) {
    __nv_fp8_e4m3 t; t.__x = (__nv_fp8_storage_t)b; return float(t);
}

// ---------------- prep kernel ----------------
// xpad[B,KX] fp8 = concat(motions, z, 0-pad); cols [512:640) of expert slots 0..7
// of h1e/h2e get (z | zeros). Gate slot 8 pad cols stay zero (device zero-init,
// never written) and hit zero weight rows anyway.
__global__ void prep_kernel(const float* __restrict__ motions, const float* __restrict__ z,
                            uint8_t* __restrict__ xpad,
                            uint8_t* __restrict__ h1e, uint8_t* __restrict__ h2e) {
    int idx = blockIdx.x * 256 + threadIdx.x;
    const int XT = B_ * KX;
    const int ZT = B_ * 128;
    if (idx < XT) {
        int row = idx / KX, c = idx % KX;
        float v = 0.f;
        if (c < 256)      v = motions[(size_t)row * 256 + c];
        else if (c < 288) v = z[(size_t)row * 32 + (c - 256)];
        xpad[idx] = to_fp8(v);
    } else if (idx < XT + ZT) {
        int j = idx - XT;
        int row = j / 128, c = j % 128;          // c -> col 512+c
        uint8_t v = to_fp8(c < 32 ? z[(size_t)row * 32 + c] : 0.f);
        size_t base = (size_t)row * KH + 512 + c;
#pragma unroll
        for (int e = 0; e < NE; e++) {
            h1e[(size_t)e * B_ * KH + base] = v;
            h2e[(size_t)e * B_ * KH + base] = v;
        }
    }
}

// ---------------- weight convert/transpose/pad (scale x32 into e4m3) ----------------
static constexpr int WC_C0 = NS * H * KX;       // W1t (slot 8 = gate gw1)
static constexpr int WC_C1 = NS * H * KH;       // W2t (slot 8 = gate gw2)
static constexpr int WC_C2 = NE * M_OUT * KH;   // W3t
static constexpr int WC_C3 = NS * H;            // b1arr
static constexpr int WC_C4 = NS * H;            // b2arr
static constexpr int WC_TOT = WC_C0 + WC_C1 + WC_C2 + WC_C3 + WC_C4;

__global__ void wconv_kernel(const float* __restrict__ gw1, const float* __restrict__ gw2,
                             const float* __restrict__ W1, const float* __restrict__ W2,
                             const float* __restrict__ W3,
                             const float* __restrict__ gb1, const float* __restrict__ gb2,
                             const float* __restrict__ b1, const float* __restrict__ b2,
                             uint8_t* __restrict__ W1t, uint8_t* __restrict__ W2t,
                             uint8_t* __restrict__ W3t,
                             float* __restrict__ b1a, float* __restrict__ b2a) {
    int idx = blockIdx.x * 256 + threadIdx.x;
    if (idx < WC_C0) {
        int e = idx / (H * KX); int r = idx % (H * KX); int n = r / KX, k = r % KX;
        float v = 0.f;
        if (e < NE) { if (k < 288) v = W1[((size_t)e * 288 + k) * H + n]; }
        else        { if (k < 288) v = gw1[(size_t)k * H + n]; }
        W1t[idx] = to_fp8(v * WSCALE);
        return;
    }
    idx -= WC_C0;
    if (idx < WC_C1) {
        int e = idx / (H * KH); int r = idx % (H * KH); int n = r / KH, k = r % KH;
        float v = 0.f;
        if (e < NE) { if (k < 544) v = W2[((size_t)e * 544 + k) * H + n]; }
        else        { if (k < 512) v = gw2[(size_t)k * H + n]; }
        W2t[idx] = to_fp8(v * WSCALE);
        return;
    }
    idx -= WC_C1;
    if (idx < WC_C2) {
        int e = idx / (M_OUT * KH); int r = idx % (M_OUT * KH); int n = r / KH, k = r % KH;
        float v = (k < 544) ? W3[((size_t)e * 544 + k) * M_OUT + n] : 0.f;
        W3t[idx] = to_fp8(v * WSCALE);
        return;
    }
    idx -= WC_C2;
    if (idx < WC_C3) {
        int e = idx / H, n = idx % H;
        b1a[idx] = (e < NE) ? b1[(size_t)e * H + n] : gb1[n];
        return;
    }
    idx -= WC_C3;
    if (idx < WC_C4) {
        int e = idx / H, n = idx % H;
        b2a[idx] = (e < NE) ? b2[(size_t)e * H + n] : gb2[n];
    }
}

// ---------------- FP8 MMA GEMM: C = elu(A @ Bt / 32 + bias) ----------------
// 256 threads, tile 128x128, K-chunks of 128 fp8 (128B rows), 3-stage cp.async ring,
// 2 CTAs/SM. Warps 2(M) x 4(N); warp tile 64x32. Fragment double-buffer over 4 kk
// (k=32 each). Output fp8 (hidden layers) or bf16 (layer 3), selected by out_bf16.
static constexpr int STAGE_BYTES = 16384 + 16384;
static constexpr int NSTAGE      = 3;
static constexpr int SMEM_BYTES  = 1024 + NSTAGE * STAGE_BYTES; // 99328

__global__ __launch_bounds__(256, 2)
void gemm_bias_elu(const uint8_t* __restrict__ A, int lda, size_t a_es,
                   const uint8_t* __restrict__ Bw, int ldb, size_t b_es,
                   const float* __restrict__ bias, int bias_es,
                   void* __restrict__ Cv, int ldc, size_t c_es, int kchunks, int out_bf16) {
    extern __shared__ unsigned char smem[];
    float* sbias = (float*)smem;
    unsigned char* tiles = smem + 1024;
    const uint32_t tiles_u = smem_u32(tiles);
    const int tid = threadIdx.x;
    const int e  = blockIdx.z;
    const int m0 = blockIdx.x * 128, n0 = blockIdx.y * 128;
    A    += (size_t)e * a_es;
    Bw   += (size_t)e * b_es;
    bias += (size_t)e * bias_es;

    if (tid < 128) sbias[tid] = bias[n0 + tid];

    // --- loader: each thread owns 4 consecutive 16B segs of one 128B row per tile ---
    const int lr = tid >> 1;                 // row 0..127
    const uint32_t lbase = (tid & 1) * 64;   // 0 or 64 bytes
    const uint8_t* gA = A + (size_t)(m0 + lr) * lda + lbase;
    const uint8_t* gB = Bw + (size_t)(n0 + lr) * ldb + lbase;
    const uint32_t su   = (uint32_t)lr * 128 + lbase;
    const uint32_t sxor = (su >> 3) & 0x70;

    auto load_stage = [&](int s, int buf) {
        uint32_t ab = tiles_u + buf * STAGE_BYTES;
        uint32_t bb = ab + 16384;
        const uint8_t* a = gA + (size_t)s * 128;
        const uint8_t* b = gB + (size_t)s * 128;
#pragma unroll
        for (int i = 0; i < 4; i++) {
            uint32_t so = (su + i * 16) ^ sxor;
            cp16(ab + so, a + i * 16);
            cp16(bb + so, b + i * 16);
        }
        asm volatile("cp.async.commit_group;" ::: "memory");
    };

    load_stage(0, 0);
    load_stage(1, 1);

    const int lane = tid & 31, w = tid >> 5;
    const int wm = (w >> 2) * 64;
    const int wn = (w & 3) * 32;
    const int arow = lane & 15, ahalf = (lane >> 4) * 16;

    // kk advances by XOR with kk*32 (bits 5-6 of base are zero; swizzle bits from rows only)
    uint32_t pa[4], pb[2];
#pragma unroll
    for (int mf = 0; mf < 4; mf++)
        pa[mf] = swz128((uint32_t)((wm + mf * 16 + arow) * 128 + ahalf));
#pragma unroll
    for (int p = 0; p < 2; p++)
        pb[p] = swz128((uint32_t)((wn + p * 16 + arow) * 128 + ahalf));

    float acc[4][4][4];
#pragma unroll
    for (int mf = 0; mf < 4; mf++)
#pragma unroll
        for (int nf = 0; nf < 4; nf++)
#pragma unroll
            for (int i = 0; i < 4; i++) acc[mf][nf][i] = 0.f;

    int buf = 0, nbuf = 2;
    for (int s = 0; s < kchunks; s++) {
        asm volatile("cp.async.wait_group 1;" ::: "memory");
        __syncthreads();
        if (s + 2 < kchunks) load_stage(s + 2, nbuf);
        else asm volatile("cp.async.commit_group;" ::: "memory");

        uint32_t abase = tiles_u + buf * STAGE_BYTES;
        uint32_t bbase = abase + 16384;

        uint32_t af[2][4][4], bf[2][2][4];
#pragma unroll
        for (int mf = 0; mf < 4; mf++)
            ldsm_x4(af[0][mf][0], af[0][mf][1], af[0][mf][2], af[0][mf][3], abase + pa[mf]);
#pragma unroll
        for (int p = 0; p < 2; p++)
            ldsm_x4(bf[0][p][0], bf[0][p][1], bf[0][p][2], bf[0][p][3], bbase + pb[p]);

#pragma unroll
        for (int kk = 0; kk < 4; kk++) {        // 4 x k32 = 128 fp8 per chunk
            const int cur = kk & 1, nxt = cur ^ 1;
            if (kk < 3) {
                const uint32_t kx = (uint32_t)((kk + 1) * 32);
#pragma unroll
                for (int mf = 0; mf < 4; mf++)
                    ldsm_x4(af[nxt][mf][0], af[nxt][mf][1], af[nxt][mf][2], af[nxt][mf][3],
                            abase + (pa[mf] ^ kx));
#pragma unroll
                for (int p = 0; p < 2; p++)
                    ldsm_x4(bf[nxt][p][0], bf[nxt][p][1], bf[nxt][p][2], bf[nxt][p][3],
                            bbase + (pb[p] ^ kx));
            }
#pragma unroll
            for (int mf = 0; mf < 4; mf++) {
#pragma unroll
                for (int p = 0; p < 2; p++) {
                    mma16832(acc[mf][2 * p],     af[cur][mf][0], af[cur][mf][1],
                             af[cur][mf][2], af[cur][mf][3], bf[cur][p][0], bf[cur][p][2]);
                    mma16832(acc[mf][2 * p + 1], af[cur][mf][0], af[cur][mf][1],
                             af[cur][mf][2], af[cur][mf][3], bf[cur][p][1], bf[cur][p][3]);
                }
            }
        }
        buf = (buf == 2) ? 0 : buf + 1;
        nbuf = (nbuf == 2) ? 0 : nbuf + 1;
    }

    // ---- epilogue: acc/32 + bias, ELU, store fp8 or bf16 ----
    const int cg = lane >> 2;
    const int cc = (lane & 3) * 2;
#pragma unroll
    for (int mf = 0; mf < 4; mf++) {
        int r0 = m0 + wm + mf * 16 + cg;
        int r1 = r0 + 8;
#pragma unroll
        for (int nf = 0; nf < 4; nf++) {
            int col = wn + nf * 8 + cc;
            float b0 = sbias[col], b1v = sbias[col + 1];
            float v0 = acc[mf][nf][0] * IWSCALE + b0, v1 = acc[mf][nf][1] * IWSCALE + b1v;
            float v2 = acc[mf][nf][2] * IWSCALE + b0, v3 = acc[mf][nf][3] * IWSCALE + b1v;
            v0 = v0 > 0.f ? v0 : (__expf(v0) - 1.f);
            v1 = v1 > 0.f ? v1 : (__expf(v1) - 1.f);
            v2 = v2 > 0.f ? v2 : (__expf(v2) - 1.f);
            v3 = v3 > 0.f ? v3 : (__expf(v3) - 1.f);
            if (out_bf16) {
                __nv_bfloat16* C = (__nv_bfloat16*)Cv + (size_t)e * c_es;
                *(__nv_bfloat162*)(C + (size_t)r0 * ldc + n0 + col) = __floats2bfloat162_rn(v0, v1);
                *(__nv_bfloat162*)(C + (size_t)r1 * ldc + n0 + col) = __floats2bfloat162_rn(v2, v3);
            } else {
                uint8_t* C = (uint8_t*)Cv + (size_t)e * c_es;
                uint16_t p0 = (uint16_t)to_fp8(v0) | ((uint16_t)to_fp8(v1) << 8);
                uint16_t p1 = (uint16_t)to_fp8(v2) | ((uint16_t)to_fp8(v3) << 8);
                *(uint16_t*)(C + (size_t)r0 * ldc + n0 + col) = p0;
                *(uint16_t*)(C + (size_t)r1 * ldc + n0 + col) = p1;
            }
        }
    }
}

// ---------------- gate layer 3 (N=8) + deterministic partial norm ----------------
// g2 rows: fp8, stride KH, first 512 cols valid.
__global__ void gate3_kernel(const uint8_t* __restrict__ g2,
                             const float* __restrict__ gw3, const float* __restrict__ gb3,
                             float* __restrict__ para, float* __restrict__ partial) {
    __shared__ float sw[8 * 512];
    __shared__ float wsum[8];
    int tid = threadIdx.x;
    for (int i = tid; i < 4096; i += 256) { int k = i / 8, e = i % 8; sw[e * 512 + k] = gw3[k * 8 + e]; }
    __syncthreads();
    int warp = tid / 32, lane = tid % 32;
    int row = blockIdx.x * 8 + warp;
    float acc[8];
#pragma unroll
    for (int e = 0; e < 8; e++) acc[e] = 0.f;
    const uint32_t* gr = (const uint32_t*)(g2 + (size_t)row * KH);
#pragma unroll
    for (int i = 0; i < 4; i++) {
        uint32_t u = gr[i * 32 + lane];
        int k0 = i * 128 + lane * 4;
#pragma unroll
        for (int b = 0; b < 4; b++) {
            float a = from_fp8((uint8_t)(u >> (8 * b)));
#pragma unroll
            for (int e = 0; e < 8; e++) acc[e] += a * sw[e * 512 + k0 + b];
        }
    }
#pragma unroll
    for (int off = 16; off; off >>= 1)
#pragma unroll
        for (int e = 0; e < 8; e++) acc[e] += __shfl_down_sync(0xFFFFFFFFu, acc[e], off);
    if (lane == 0) {
        float ss = 0.f;
#pragma unroll
        for (int e = 0; e < 8; e++) {
            float v = acc[e] + gb3[e];
            v = v > 0.f ? v : (__expf(v) - 1.f);
            para[(size_t)row * 8 + e] = v;
            ss += v * v;
        }
        wsum[warp] = ss;
    }
    __syncthreads();
    if (tid == 0) {
        float s = 0.f;
        for (int w = 0; w < 8; w++) s += wsum[w];
        partial[blockIdx.x] = s;
    }
}

__global__ void reduce_norm_kernel(const float* __restrict__ partial, float* __restrict__ invnorm) {
    __shared__ float s[256];
    int tid = threadIdx.x;
    float v = 0.f;
    for (int k = 0; k < 8; k++) v += partial[tid + k * 256];
    s[tid] = v;
    __syncthreads();
    for (int off = 128; off; off >>= 1) {
        if (tid < off) s[tid] += s[tid + off];
        __syncthreads();
    }
    if (tid == 0) *invnorm = rsqrtf(s[0]);
}

// ---------------- combine ----------------
__global__ void combine_kernel(const float* __restrict__ para, const __nv_bfloat16* __restrict__ h3,
                               const float* __restrict__ invnorm, float* __restrict__ out) {
    int t = blockIdx.x * 256 + threadIdx.x;
    int b = t >> 7;
    float inv = *invnorm;
    float4 p0 = ((const float4*)para)[b * 2];
    float4 p1 = ((const float4*)para)[b * 2 + 1];
    float pe[8] = {p0.x, p0.y, p0.z, p0.w, p1.x, p1.y, p1.z, p1.w};
    float acc = 0.f;
#pragma unroll
    for (int e = 0; e < 8; e++)
        acc += pe[e] * __bfloat162float(h3[(size_t)e * B_ * M_OUT + t]);
    float x = acc * inv;
    out[t] = 1.f / (1.f + __expf(-x));
}

// ---------------- host launcher ----------------
extern "C" void kernel_launch(void* const* d_in, const int* in_sizes, int n_in,
                              void* d_out, int out_size) {
    const float* motions = (const float*)d_in[0];
    const float* z       = (const float*)d_in[1];
    const float* gw1     = (const float*)d_in[2];
    const float* gb1     = (const float*)d_in[3];
    const float* gw2     = (const float*)d_in[4];
    const float* gb2     = (const float*)d_in[5];
    const float* gw3     = (const float*)d_in[6];
    const float* gb3     = (const float*)d_in[7];
    const float* W1      = (const float*)d_in[8];
    const float* b1      = (const float*)d_in[9];
    const float* W2      = (const float*)d_in[10];
    const float* b2      = (const float*)d_in[11];
    const float* W3      = (const float*)d_in[12];
    const float* b3      = (const float*)d_in[13];
    float* out = (float*)d_out;

    unsigned char* sc = nullptr;
    cudaGetSymbolAddress((void**)&sc, g_scratch);
    uint8_t* xpad = (uint8_t*)(sc + OFF_XPAD);
    uint8_t* h1e  = (uint8_t*)(sc + OFF_H1);
    uint8_t* h2e  = (uint8_t*)(sc + OFF_H2);
    __nv_bfloat16* h3 = (__nv_bfloat16*)(sc + OFF_H3);
    float* para = (float*)(sc + OFF_PARA);
    float* part = (float*)(sc + OFF_PART);
    float* inv  = (float*)(sc + OFF_INV);
    uint8_t* W1t = (uint8_t*)(sc + OFF_W1T);
    uint8_t* W2t = (uint8_t*)(sc + OFF_W2T);
    uint8_t* W3t = (uint8_t*)(sc + OFF_W3T);
    float* b1a = (float*)(sc + OFF_B1A);
    float* b2a = (float*)(sc + OFF_B2A);

    cudaFuncSetAttribute(gemm_bias_elu, cudaFuncAttributeMaxDynamicSharedMemorySize, SMEM_BYTES);

    const int PREP_T = B_ * (KX + 128);
    prep_kernel<<<(PREP_T + 255) / 256, 256>>>(motions, z, xpad, h1e, h2e);
    wconv_kernel<<<(WC_TOT + 255) / 256, 256>>>(gw1, gw2, W1, W2, W3, gb1, gb2, b1, b2,
                                                W1t, W2t, W3t, b1a, b2a);

    dim3 gL12(B_ / 128, 4, NS);   // 9 z-slices: experts 0..7 + gate
    dim3 gL3(B_ / 128, 1, NE);

    // Layer 1 (fp8 out): xpad [B,KX] @ W1t -> h1e slots
    gemm_bias_elu<<<gL12, 256, SMEM_BYTES>>>(xpad, KX, 0,
                                             W1t, KX, (size_t)H * KX,
                                             b1a, H,
                                             h1e, KH, (size_t)B_ * KH, KX / 128, 0);
    // Layer 2 (fp8 out)
    gemm_bias_elu<<<gL12, 256, SMEM_BYTES>>>(h1e, KH, (size_t)B_ * KH,
                                             W2t, KH, (size_t)H * KH,
                                             b2a, H,
                                             h2e, KH, (size_t)B_ * KH, KH / 128, 0);
    // gate layer 3 + norm (reads h2e slot 8)
    gate3_kernel<<<B_ / 8, 256>>>(h2e + (size_t)NE * B_ * KH, gw3, gb3, para, part);
    reduce_norm_kernel<<<1, 256>>>(part, inv);

    // Layer 3 (bf16 out, experts only)
    gemm_bias_elu<<<gL3, 256, SMEM_BYTES>>>(h2e, KH, (size_t)B_ * KH,
                                            W3t, KH, (size_t)M_OUT * KH,
                                            b3, M_OUT,
                                            h3, M_OUT, (size_t)B_ * M_OUT, KH / 128, 1);

    combine_kernel<<<(B_ * M_OUT) / 256, 256>>>(para, h3, inv, out);
}

// round 8
// speedup vs baseline: 1.0867x; 1.0867x over previous
#include <cuda_runtime.h>
#include <cuda_bf16.h>
#include <stdint.h>

// ---------------- problem constants ----------------
static constexpr int B_    = 16384;
static constexpr int KX    = 320;   // padded input K (288 -> 320)
static constexpr int KH    = 576;   // padded hidden K (512 + 32 z + 32 pad)
static constexpr int H     = 512;
static constexpr int M_OUT = 128;
static constexpr int NE    = 8;
static constexpr int NS    = NE + 1; // 8 experts + gate slot

// ---------------- scratch layout (single __device__ array) ----------------
static constexpr size_t OFF_XPAD = 0;
static constexpr size_t SZ_XPAD  = (size_t)B_*KX*2;
static constexpr size_t OFF_H1   = OFF_XPAD + SZ_XPAD;
static constexpr size_t SZ_HEXT  = (size_t)NS*B_*KH*2;      // 9 slots (slot 8 = gate)
static constexpr size_t OFF_H2   = OFF_H1 + SZ_HEXT;
static constexpr size_t OFF_H3   = OFF_H2 + SZ_HEXT;
static constexpr size_t SZ_H3    = (size_t)NE*B_*M_OUT*2;
static constexpr size_t OFF_PARA = OFF_H3 + SZ_H3;
static constexpr size_t SZ_PARA  = (size_t)B_*NE*4;
static constexpr size_t OFF_PART = OFF_PARA + SZ_PARA;
static constexpr size_t SZ_PART  = 2048*4;
static constexpr size_t OFF_INV  = OFF_PART + SZ_PART;
static constexpr size_t SZ_INV   = 256;
static constexpr size_t OFF_W1T  = OFF_INV + SZ_INV;
static constexpr size_t SZ_W1T   = (size_t)NS*H*KX*2;
static constexpr size_t OFF_W2T  = OFF_W1T + SZ_W1T;
static constexpr size_t SZ_W2T   = (size_t)NS*H*KH*2;
static constexpr size_t OFF_W3T  = OFF_W2T + SZ_W2T;
static constexpr size_t SZ_W3T   = (size_t)NE*M_OUT*KH*2;
static constexpr size_t OFF_B1A  = OFF_W3T + SZ_W3T;
static constexpr size_t SZ_B1A   = (size_t)NS*H*4;
static constexpr size_t OFF_B2A  = OFF_B1A + SZ_B1A;
static constexpr size_t SZ_B2A   = (size_t)NS*H*4;
static constexpr size_t SCRATCH_TOTAL = OFF_B2A + SZ_B2A;

__device__ __align__(1024) unsigned char g_scratch[SCRATCH_TOTAL];

// ---------------- helpers ----------------
__device__ __forceinline__ uint32_t smem_u32(const void* p) {
    return (uint32_t)__cvta_generic_to_shared(p);
}
__device__ __forceinline__ uint32_t swz128(uint32_t off) {
    return off ^ ((off >> 3) & 0x70);
}
__device__ __forceinline__ void cp16(uint32_t dst, const void* src) {
    asm volatile("cp.async.cg.shared.global [%0], [%1], 16;\n" :: "r"(dst), "l"(src) : "memory");
}
__device__ __forceinline__ void ldsm_x4(uint32_t& r0, uint32_t& r1, uint32_t& r2, uint32_t& r3,
                                        uint32_t addr) {
    asm volatile("ldmatrix.sync.aligned.m8n8.x4.shared.b16 {%0,%1,%2,%3}, [%4];"
                 : "=r"(r0), "=r"(r1), "=r"(r2), "=r"(r3) : "r"(addr));
}
__device__ __forceinline__ void mma16816(float* c, uint32_t a0, uint32_t a1, uint32_t a2, uint32_t a3,
                                         uint32_t b0, uint32_t b1) {
    asm volatile(
        "mma.sync.aligned.m16n8k16.row.col.f32.bf16.bf16.f32 "
        "{%0,%1,%2,%3}, {%4,%5,%6,%7}, {%8,%9}, {%0,%1,%2,%3};"
        : "+f"(c[0]), "+f"(c[1]), "+f"(c[2]), "+f"(c[3])
        : "r"(a0), "r"(a1), "r"(a2), "r"(a3), "r"(b0), "r"(b1));
}

// ---------------- prep kernel ----------------
// xpad[B,KX] = concat(motions, z, 0-pad); z-columns [512:576) of expert slots 0..7
// of h1e/h2e. Gate slot (8) z-cols stay zero (device global zero-init, never written)
// and are multiplied by zero weight rows anyway.
__global__ void prep_kernel(const float* __restrict__ motions, const float* __restrict__ z,
                            __nv_bfloat16* __restrict__ xpad,
                            __nv_bfloat16* __restrict__ h1e, __nv_bfloat16* __restrict__ h2e) {
    int idx = blockIdx.x * 256 + threadIdx.x;
    const int XT = B_ * KX;
    const int ZT = B_ * 64;
    if (idx < XT) {
        int row = idx / KX, c = idx % KX;
        float v = 0.f;
        if (c < 256)      v = motions[(size_t)row * 256 + c];
        else if (c < 288) v = z[(size_t)row * 32 + (c - 256)];
        xpad[idx] = __float2bfloat16(v);
    } else if (idx < XT + ZT) {
        int j = idx - XT;
        int row = j / 64, c = j % 64;
        __nv_bfloat16 v = __float2bfloat16(c < 32 ? z[(size_t)row * 32 + c] : 0.f);
        size_t base = (size_t)row * KH + 512 + c;
#pragma unroll
        for (int e = 0; e < NE; e++) {
            h1e[(size_t)e * B_ * KH + base] = v;
            h2e[(size_t)e * B_ * KH + base] = v;
        }
    }
}

// ---------------- weight convert/transpose/pad kernel ----------------
static constexpr int WC_C0 = NS * H * KX;       // W1t (slot 8 = gate gw1)
static constexpr int WC_C1 = NS * H * KH;       // W2t (slot 8 = gate gw2, K padded)
static constexpr int WC_C2 = NE * M_OUT * KH;   // W3t
static constexpr int WC_C3 = NS * H;            // b1arr
static constexpr int WC_C4 = NS * H;            // b2arr
static constexpr int WC_TOT = WC_C0 + WC_C1 + WC_C2 + WC_C3 + WC_C4;

__global__ void wconv_kernel(const float* __restrict__ gw1, const float* __restrict__ gw2,
                             const float* __restrict__ W1, const float* __restrict__ W2,
                             const float* __restrict__ W3,
                             const float* __restrict__ gb1, const float* __restrict__ gb2,
                             const float* __restrict__ b1, const float* __restrict__ b2,
                             __nv_bfloat16* __restrict__ W1t, __nv_bfloat16* __restrict__ W2t,
                             __nv_bfloat16* __restrict__ W3t,
                             float* __restrict__ b1a, float* __restrict__ b2a) {
    int idx = blockIdx.x * 256 + threadIdx.x;
    if (idx < WC_C0) {
        int e = idx / (H * KX); int r = idx % (H * KX); int n = r / KX, k = r % KX;
        float v = 0.f;
        if (e < NE) { if (k < 288) v = W1[((size_t)e * 288 + k) * H + n]; }
        else        { if (k < 288) v = gw1[(size_t)k * H + n]; }
        W1t[idx] = __float2bfloat16(v);
        return;
    }
    idx -= WC_C0;
    if (idx < WC_C1) {
        int e = idx / (H * KH); int r = idx % (H * KH); int n = r / KH, k = r % KH;
        float v = 0.f;
        if (e < NE) { if (k < 544) v = W2[((size_t)e * 544 + k) * H + n]; }
        else        { if (k < 512) v = gw2[(size_t)k * H + n]; }
        W2t[idx] = __float2bfloat16(v);
        return;
    }
    idx -= WC_C1;
    if (idx < WC_C2) {
        int e = idx / (M_OUT * KH); int r = idx % (M_OUT * KH); int n = r / KH, k = r % KH;
        W3t[idx] = __float2bfloat16(k < 544 ? W3[((size_t)e * 544 + k) * M_OUT + n] : 0.f);
        return;
    }
    idx -= WC_C2;
    if (idx < WC_C3) {
        int e = idx / H, n = idx % H;
        b1a[idx] = (e < NE) ? b1[(size_t)e * H + n] : gb1[n];
        return;
    }
    idx -= WC_C3;
    if (idx < WC_C4) {
        int e = idx / H, n = idx % H;
        b2a[idx] = (e < NE) ? b2[(size_t)e * H + n] : gb2[n];
    }
}

// ---------------- HMMA GEMM: C[m,n] = elu(sum_k A[m,k]*Bt[n,k] + bias[n]) -> bf16 ----------------
// OCCUPANCY EXPERIMENT: CTA tile 64(M) x 128(N), 256 threads, warp tile 32x32
// (acc = 32 regs/thread), __launch_bounds__(256,3) -> ~80 regs -> 3 CTAs/SM = 24 warps.
// K-chunks of 64, 3-stage cp.async ring, one __syncthreads per chunk.
static constexpr int A_TILE_B    = 64 * 128;        // 8 KB
static constexpr int B_TILE_B    = 128 * 128;       // 16 KB
static constexpr int STAGE_BYTES = A_TILE_B + B_TILE_B;          // 24 KB
static constexpr int NSTAGE      = 3;
static constexpr int SMEM_BYTES  = 1024 + NSTAGE * STAGE_BYTES;  // 74752

__global__ __launch_bounds__(256, 3)
void gemm_bias_elu(const __nv_bfloat16* __restrict__ A, int lda, size_t a_es,
                   const __nv_bfloat16* __restrict__ Bw, int ldb, size_t b_es,
                   const float* __restrict__ bias, int bias_es,
                   __nv_bfloat16* __restrict__ C, int ldc, size_t c_es, int kchunks) {
    extern __shared__ unsigned char smem[];
    float* sbias = (float*)smem;
    unsigned char* tiles = smem + 1024;
    const uint32_t tiles_u = smem_u32(tiles);
    const int tid = threadIdx.x;
    const int e  = blockIdx.z;
    const int m0 = blockIdx.x * 64, n0 = blockIdx.y * 128;
    A    += (size_t)e * a_es;
    Bw   += (size_t)e * b_es;
    bias += (size_t)e * bias_es;
    C    += (size_t)e * c_es;

    if (tid < 128) sbias[tid] = bias[n0 + tid];

    // --- loaders ---
    // A: 64 rows x 128B. 512 segs of 16B; thread owns 2 consecutive segs.
    const int arow_l = tid >> 2;                    // 0..63
    const uint32_t aseg = (uint32_t)(tid & 3) * 32; // 0,32,64,96
    const char* gAr = (const char*)A + ((size_t)(m0 + arow_l) * lda) * 2 + aseg;
    const uint32_t suA = (uint32_t)arow_l * 128 + aseg;
    const uint32_t sxA = (suA >> 3) & 0x70;
    // B: 128 rows x 128B. 1024 segs; thread owns 4 consecutive segs.
    const int brow_l = tid >> 1;                    // 0..127
    const uint32_t bseg = (uint32_t)(tid & 1) * 64; // 0 or 64
    const char* gBr = (const char*)Bw + ((size_t)(n0 + brow_l) * ldb) * 2 + bseg;
    const uint32_t suB = (uint32_t)brow_l * 128 + bseg;
    const uint32_t sxB = (suB >> 3) & 0x70;

    auto load_stage = [&](int s, int buf) {
        uint32_t ab = tiles_u + buf * STAGE_BYTES;
        uint32_t bb = ab + A_TILE_B;
        const char* a = gAr + (size_t)s * 128;
        const char* b = gBr + (size_t)s * 128;
#pragma unroll
        for (int i = 0; i < 2; i++) cp16(ab + ((suA + i * 16) ^ sxA), a + i * 16);
#pragma unroll
        for (int i = 0; i < 4; i++) cp16(bb + ((suB + i * 16) ^ sxB), b + i * 16);
        asm volatile("cp.async.commit_group;" ::: "memory");
    };

    load_stage(0, 0);
    load_stage(1, 1);

    const int lane = tid & 31, w = tid >> 5;
    const int wm = (w >> 2) * 32;       // warp M offset: 0 or 32
    const int wn = (w & 3) * 32;        // warp N offset: 0,32,64,96
    const int arow = lane & 15, ahalf = (lane >> 4) * 16;

    // kk advances by XOR with kk*32 (base bits 5-6 zero; swizzle bits from rows only)
    uint32_t pa[2], pb[2];
#pragma unroll
    for (int mf = 0; mf < 2; mf++)
        pa[mf] = swz128((uint32_t)((wm + mf * 16 + arow) * 128 + ahalf));
#pragma unroll
    for (int p = 0; p < 2; p++)
        pb[p] = swz128((uint32_t)((wn + p * 16 + arow) * 128 + ahalf));

    float acc[2][4][4];
#pragma unroll
    for (int mf = 0; mf < 2; mf++)
#pragma unroll
        for (int nf = 0; nf < 4; nf++)
#pragma unroll
            for (int i = 0; i < 4; i++) acc[mf][nf][i] = 0.f;

    int buf = 0, nbuf = 2;
    for (int s = 0; s < kchunks; s++) {
        asm volatile("cp.async.wait_group 1;" ::: "memory");
        __syncthreads();
        if (s + 2 < kchunks) load_stage(s + 2, nbuf);
        else asm volatile("cp.async.commit_group;" ::: "memory");

        uint32_t abase = tiles_u + buf * STAGE_BYTES;
        uint32_t bbase = abase + A_TILE_B;
#pragma unroll
        for (int kk = 0; kk < 4; kk++) {
            const uint32_t kx = (uint32_t)(kk * 32);
            uint32_t af[2][4], bf[2][4];
#pragma unroll
            for (int mf = 0; mf < 2; mf++)
                ldsm_x4(af[mf][0], af[mf][1], af[mf][2], af[mf][3], abase + (pa[mf] ^ kx));
#pragma unroll
            for (int p = 0; p < 2; p++)
                ldsm_x4(bf[p][0], bf[p][1], bf[p][2], bf[p][3], bbase + (pb[p] ^ kx));
#pragma unroll
            for (int mf = 0; mf < 2; mf++) {
#pragma unroll
                for (int p = 0; p < 2; p++) {
                    mma16816(acc[mf][2 * p],     af[mf][0], af[mf][1], af[mf][2], af[mf][3],
                             bf[p][0], bf[p][2]);
                    mma16816(acc[mf][2 * p + 1], af[mf][0], af[mf][1], af[mf][2], af[mf][3],
                             bf[p][1], bf[p][3]);
                }
            }
        }
        buf = (buf == 2) ? 0 : buf + 1;
        nbuf = (nbuf == 2) ? 0 : nbuf + 1;
    }

    // ---- epilogue: bias + ELU + bf16 store ----
    const int cg = lane >> 2;
    const int cc = (lane & 3) * 2;
#pragma unroll
    for (int mf = 0; mf < 2; mf++) {
        int r0 = m0 + wm + mf * 16 + cg;
        int r1 = r0 + 8;
#pragma unroll
        for (int nf = 0; nf < 4; nf++) {
            int col = wn + nf * 8 + cc;
            float b0 = sbias[col], b1v = sbias[col + 1];
            float v0 = acc[mf][nf][0] + b0, v1 = acc[mf][nf][1] + b1v;
            float v2 = acc[mf][nf][2] + b0, v3 = acc[mf][nf][3] + b1v;
            v0 = v0 > 0.f ? v0 : (__expf(v0) - 1.f);
            v1 = v1 > 0.f ? v1 : (__expf(v1) - 1.f);
            v2 = v2 > 0.f ? v2 : (__expf(v2) - 1.f);
            v3 = v3 > 0.f ? v3 : (__expf(v3) - 1.f);
            *(__nv_bfloat162*)(C + (size_t)r0 * ldc + n0 + col) = __floats2bfloat162_rn(v0, v1);
            *(__nv_bfloat162*)(C + (size_t)r1 * ldc + n0 + col) = __floats2bfloat162_rn(v2, v3);
        }
    }
}

// ---------------- gate layer 3 (N=8) + deterministic partial norm ----------------
// g2 rows live in h2e slot 8 with row stride KH (first 512 cols valid).
__global__ void gate3_kernel(const __nv_bfloat16* __restrict__ g2,
                             const float* __restrict__ gw3, const float* __restrict__ gb3,
                             float* __restrict__ para, float* __restrict__ partial) {
    __shared__ float sw[8 * 512];
    __shared__ float wsum[8];
    int tid = threadIdx.x;
    for (int i = tid; i < 4096; i += 256) { int k = i / 8, e = i % 8; sw[e * 512 + k] = gw3[k * 8 + e]; }
    __syncthreads();
    int warp = tid / 32, lane = tid % 32;
    int row = blockIdx.x * 8 + warp;
    float acc[8];
#pragma unroll
    for (int e = 0; e < 8; e++) acc[e] = 0.f;
    const __nv_bfloat162* gr = (const __nv_bfloat162*)(g2 + (size_t)row * KH);
#pragma unroll
    for (int i = 0; i < 8; i++) {
        __nv_bfloat162 p = gr[i * 32 + lane];
        float a0 = __bfloat162float(p.x), a1 = __bfloat162float(p.y);
        int k0 = i * 64 + lane * 2;
#pragma unroll
        for (int e = 0; e < 8; e++) acc[e] += a0 * sw[e * 512 + k0] + a1 * sw[e * 512 + k0 + 1];
    }
#pragma unroll
    for (int off = 16; off; off >>= 1)
#pragma unroll
        for (int e = 0; e < 8; e++) acc[e] += __shfl_down_sync(0xFFFFFFFFu, acc[e], off);
    if (lane == 0) {
        float ss = 0.f;
#pragma unroll
        for (int e = 0; e < 8; e++) {
            float v = acc[e] + gb3[e];
            v = v > 0.f ? v : (__expf(v) - 1.f);
            para[(size_t)row * 8 + e] = v;
            ss += v * v;
        }
        wsum[warp] = ss;
    }
    __syncthreads();
    if (tid == 0) {
        float s = 0.f;
        for (int w = 0; w < 8; w++) s += wsum[w];
        partial[blockIdx.x] = s;
    }
}

__global__ void reduce_norm_kernel(const float* __restrict__ partial, float* __restrict__ invnorm) {
    __shared__ float s[256];
    int tid = threadIdx.x;
    float v = 0.f;
    for (int k = 0; k < 8; k++) v += partial[tid + k * 256];
    s[tid] = v;
    __syncthreads();
    for (int off = 128; off; off >>= 1) {
        if (tid < off) s[tid] += s[tid + off];
        __syncthreads();
    }
    if (tid == 0) *invnorm = rsqrtf(s[0]);
}

// ---------------- combine ----------------
__global__ void combine_kernel(const float* __restrict__ para, const __nv_bfloat16* __restrict__ h3,
                               const float* __restrict__ invnorm, float* __restrict__ out) {
    int t = blockIdx.x * 256 + threadIdx.x;
    int b = t >> 7;
    float inv = *invnorm;
    float4 p0 = ((const float4*)para)[b * 2];
    float4 p1 = ((const float4*)para)[b * 2 + 1];
    float pe[8] = {p0.x, p0.y, p0.z, p0.w, p1.x, p1.y, p1.z, p1.w};
    float acc = 0.f;
#pragma unroll
    for (int e = 0; e < 8; e++)
        acc += pe[e] * __bfloat162float(h3[(size_t)e * B_ * M_OUT + t]);
    float x = acc * inv;
    out[t] = 1.f / (1.f + __expf(-x));
}

// ---------------- host launcher ----------------
extern "C" void kernel_launch(void* const* d_in, const int* in_sizes, int n_in,
                              void* d_out, int out_size) {
    const float* motions = (const float*)d_in[0];
    const float* z       = (const float*)d_in[1];
    const float* gw1     = (const float*)d_in[2];
    const float* gb1     = (const float*)d_in[3];
    const float* gw2     = (const float*)d_in[4];
    const float* gb2     = (const float*)d_in[5];
    const float* gw3     = (const float*)d_in[6];
    const float* gb3     = (const float*)d_in[7];
    const float* W1      = (const float*)d_in[8];
    const float* b1      = (const float*)d_in[9];
    const float* W2      = (const float*)d_in[10];
    const float* b2      = (const float*)d_in[11];
    const float* W3      = (const float*)d_in[12];
    const float* b3      = (const float*)d_in[13];
    float* out = (float*)d_out;

    unsigned char* sc = nullptr;
    cudaGetSymbolAddress((void**)&sc, g_scratch);
    __nv_bfloat16* xpad = (__nv_bfloat16*)(sc + OFF_XPAD);
    __nv_bfloat16* h1e  = (__nv_bfloat16*)(sc + OFF_H1);
    __nv_bfloat16* h2e  = (__nv_bfloat16*)(sc + OFF_H2);
    __nv_bfloat16* h3   = (__nv_bfloat16*)(sc + OFF_H3);
    float* para = (float*)(sc + OFF_PARA);
    float* part = (float*)(sc + OFF_PART);
    float* inv  = (float*)(sc + OFF_INV);
    __nv_bfloat16* W1t  = (__nv_bfloat16*)(sc + OFF_W1T);
    __nv_bfloat16* W2t  = (__nv_bfloat16*)(sc + OFF_W2T);
    __nv_bfloat16* W3t  = (__nv_bfloat16*)(sc + OFF_W3T);
    float* b1a = (float*)(sc + OFF_B1A);
    float* b2a = (float*)(sc + OFF_B2A);

    cudaFuncSetAttribute(gemm_bias_elu, cudaFuncAttributeMaxDynamicSharedMemorySize, SMEM_BYTES);

    const int PREP_T = B_ * (KX + 64);
    prep_kernel<<<(PREP_T + 255) / 256, 256>>>(motions, z, xpad, h1e, h2e);
    wconv_kernel<<<(WC_TOT + 255) / 256, 256>>>(gw1, gw2, W1, W2, W3, gb1, gb2, b1, b2,
                                                W1t, W2t, W3t, b1a, b2a);

    dim3 gL12(B_ / 64, 4, NS);   // 9 z-slices: experts 0..7 + gate
    dim3 gL3(B_ / 64, 1, NE);

    // Layer 1: out slot e of h1e (gate -> slot 8)
    gemm_bias_elu<<<gL12, 256, SMEM_BYTES>>>(xpad, KX, 0,
                                             W1t, KX, (size_t)H * KX,
                                             b1a, H,
                                             h1e, KH, (size_t)B_ * KH, KX / 64);
    // Layer 2
    gemm_bias_elu<<<gL12, 256, SMEM_BYTES>>>(h1e, KH, (size_t)B_ * KH,
                                             W2t, KH, (size_t)H * KH,
                                             b2a, H,
                                             h2e, KH, (size_t)B_ * KH, KH / 64);
    // gate layer 3 + norm (reads h2e slot 8)
    gate3_kernel<<<B_ / 8, 256>>>(h2e + (size_t)NE * B_ * KH, gw3, gb3, para, part);
    reduce_norm_kernel<<<1, 256>>>(part, inv);

    // Layer 3 (experts only)
    gemm_bias_elu<<<gL3, 256, SMEM_BYTES>>>(h2e, KH, (size_t)B_ * KH,
                                            W3t, KH, (size_t)M_OUT * KH,
                                            b3, M_OUT,
                                            h3, M_OUT, (size_t)B_ * M_OUT, KH / 64);

    combine_kernel<<<(B_ * M_OUT) / 256, 256>>>(para, h3, inv, out);
}

// round 9
// speedup vs baseline: 1.1333x; 1.0429x over previous
#include <cuda_runtime.h>
#include <cuda_bf16.h>
#include <stdint.h>

// ---------------- problem constants ----------------
static constexpr int B_    = 16384;
static constexpr int KX    = 320;   // padded input K storage (288 real)
static constexpr int KH    = 576;   // padded hidden K storage (544 real)
static constexpr int H     = 512;
static constexpr int M_OUT = 128;
static constexpr int NE    = 8;
static constexpr int NS    = NE + 1; // 8 experts + gate slot

// ---------------- scratch layout (single __device__ array) ----------------
static constexpr size_t OFF_XPAD = 0;
static constexpr size_t SZ_XPAD  = (size_t)B_*KX*2;
static constexpr size_t OFF_H1   = OFF_XPAD + SZ_XPAD;
static constexpr size_t SZ_HEXT  = (size_t)NS*B_*KH*2;      // 9 slots (slot 8 = gate)
static constexpr size_t OFF_H2   = OFF_H1 + SZ_HEXT;
static constexpr size_t OFF_H3   = OFF_H2 + SZ_HEXT;
static constexpr size_t SZ_H3    = (size_t)NE*B_*M_OUT*2;
static constexpr size_t OFF_PARA = OFF_H3 + SZ_H3;
static constexpr size_t SZ_PARA  = (size_t)B_*NE*4;
static constexpr size_t OFF_PART = OFF_PARA + SZ_PARA;
static constexpr size_t SZ_PART  = 2048*4;
static constexpr size_t OFF_INV  = OFF_PART + SZ_PART;
static constexpr size_t SZ_INV   = 256;
static constexpr size_t OFF_W1T  = OFF_INV + SZ_INV;
static constexpr size_t SZ_W1T   = (size_t)NS*H*KX*2;
static constexpr size_t OFF_W2T  = OFF_W1T + SZ_W1T;
static constexpr size_t SZ_W2T   = (size_t)NS*H*KH*2;
static constexpr size_t OFF_W3T  = OFF_W2T + SZ_W2T;
static constexpr size_t SZ_W3T   = (size_t)NE*M_OUT*KH*2;
static constexpr size_t OFF_B1A  = OFF_W3T + SZ_W3T;
static constexpr size_t SZ_B1A   = (size_t)NS*H*4;
static constexpr size_t OFF_B2A  = OFF_B1A + SZ_B1A;
static constexpr size_t SZ_B2A   = (size_t)NS*H*4;
static constexpr size_t SCRATCH_TOTAL = OFF_B2A + SZ_B2A;

__device__ __align__(1024) unsigned char g_scratch[SCRATCH_TOTAL];

// ---------------- helpers ----------------
__device__ __forceinline__ uint32_t smem_u32(const void* p) {
    return (uint32_t)__cvta_generic_to_shared(p);
}
__device__ __forceinline__ uint32_t swz128(uint32_t off) {
    return off ^ ((off >> 3) & 0x70);
}
__device__ __forceinline__ void cp16(uint32_t dst, const void* src) {
    asm volatile("cp.async.cg.shared.global [%0], [%1], 16;\n" :: "r"(dst), "l"(src) : "memory");
}
__device__ __forceinline__ void ldsm_x4(uint32_t& r0, uint32_t& r1, uint32_t& r2, uint32_t& r3,
                                        uint32_t addr) {
    asm volatile("ldmatrix.sync.aligned.m8n8.x4.shared.b16 {%0,%1,%2,%3}, [%4];"
                 : "=r"(r0), "=r"(r1), "=r"(r2), "=r"(r3) : "r"(addr));
}
__device__ __forceinline__ void mma16816(float* c, uint32_t a0, uint32_t a1, uint32_t a2, uint32_t a3,
                                         uint32_t b0, uint32_t b1) {
    asm volatile(
        "mma.sync.aligned.m16n8k16.row.col.f32.bf16.bf16.f32 "
        "{%0,%1,%2,%3}, {%4,%5,%6,%7}, {%8,%9}, {%0,%1,%2,%3};"
        : "+f"(c[0]), "+f"(c[1]), "+f"(c[2]), "+f"(c[3])
        : "r"(a0), "r"(a1), "r"(a2), "r"(a3), "r"(b0), "r"(b1));
}

// ---------------- prep kernel ----------------
__global__ void prep_kernel(const float* __restrict__ motions, const float* __restrict__ z,
                            __nv_bfloat16* __restrict__ xpad,
                            __nv_bfloat16* __restrict__ h1e, __nv_bfloat16* __restrict__ h2e) {
    int idx = blockIdx.x * 256 + threadIdx.x;
    const int XT = B_ * KX;
    const int ZT = B_ * 64;
    if (idx < XT) {
        int row = idx / KX, c = idx % KX;
        float v = 0.f;
        if (c < 256)      v = motions[(size_t)row * 256 + c];
        else if (c < 288) v = z[(size_t)row * 32 + (c - 256)];
        xpad[idx] = __float2bfloat16(v);
    } else if (idx < XT + ZT) {
        int j = idx - XT;
        int row = j / 64, c = j % 64;
        __nv_bfloat16 v = __float2bfloat16(c < 32 ? z[(size_t)row * 32 + c] : 0.f);
        size_t base = (size_t)row * KH + 512 + c;
#pragma unroll
        for (int e = 0; e < NE; e++) {
            h1e[(size_t)e * B_ * KH + base] = v;
            h2e[(size_t)e * B_ * KH + base] = v;
        }
    }
}

// ---------------- weight convert/transpose/pad kernel ----------------
static constexpr int WC_C0 = NS * H * KX;       // W1t (slot 8 = gate gw1)
static constexpr int WC_C1 = NS * H * KH;       // W2t (slot 8 = gate gw2, K padded)
static constexpr int WC_C2 = NE * M_OUT * KH;   // W3t
static constexpr int WC_C3 = NS * H;            // b1arr
static constexpr int WC_C4 = NS * H;            // b2arr
static constexpr int WC_TOT = WC_C0 + WC_C1 + WC_C2 + WC_C3 + WC_C4;

__global__ void wconv_kernel(const float* __restrict__ gw1, const float* __restrict__ gw2,
                             const float* __restrict__ W1, const float* __restrict__ W2,
                             const float* __restrict__ W3,
                             const float* __restrict__ gb1, const float* __restrict__ gb2,
                             const float* __restrict__ b1, const float* __restrict__ b2,
                             __nv_bfloat16* __restrict__ W1t, __nv_bfloat16* __restrict__ W2t,
                             __nv_bfloat16* __restrict__ W3t,
                             float* __restrict__ b1a, float* __restrict__ b2a) {
    int idx = blockIdx.x * 256 + threadIdx.x;
    if (idx < WC_C0) {
        int e = idx / (H * KX); int r = idx % (H * KX); int n = r / KX, k = r % KX;
        float v = 0.f;
        if (e < NE) { if (k < 288) v = W1[((size_t)e * 288 + k) * H + n]; }
        else        { if (k < 288) v = gw1[(size_t)k * H + n]; }
        W1t[idx] = __float2bfloat16(v);
        return;
    }
    idx -= WC_C0;
    if (idx < WC_C1) {
        int e = idx / (H * KH); int r = idx % (H * KH); int n = r / KH, k = r % KH;
        float v = 0.f;
        if (e < NE) { if (k < 544) v = W2[((size_t)e * 544 + k) * H + n]; }
        else        { if (k < 512) v = gw2[(size_t)k * H + n]; }
        W2t[idx] = __float2bfloat16(v);
        return;
    }
    idx -= WC_C1;
    if (idx < WC_C2) {
        int e = idx / (M_OUT * KH); int r = idx % (M_OUT * KH); int n = r / KH, k = r % KH;
        W3t[idx] = __float2bfloat16(k < 544 ? W3[((size_t)e * 544 + k) * M_OUT + n] : 0.f);
        return;
    }
    idx -= WC_C2;
    if (idx < WC_C3) {
        int e = idx / H, n = idx % H;
        b1a[idx] = (e < NE) ? b1[(size_t)e * H + n] : gb1[n];
        return;
    }
    idx -= WC_C3;
    if (idx < WC_C4) {
        int e = idx / H, n = idx % H;
        b2a[idx] = (e < NE) ? b2[(size_t)e * H + n] : gb2[n];
    }
}

// ---------------- HMMA GEMM: C[m,n] = elu(sum_k A[m,k]*Bt[n,k] + bias[n]) -> bf16 ----------------
// Best-measured config (R6): 256 threads, tile 128x128, K-chunks of 64, 3-stage cp.async
// ring, 2 CTAs/SM, warps 2(M)x4(N), warp tile 64x32, fragment double-buffer.
// NEW: the LAST chunk computes only 2 of 4 kk-steps (real K ends 32 cols into it; the
// remaining cols are exact zeros in both operands, so their MMAs are skipped).
static constexpr int STAGE_BYTES = 16384 + 16384;
static constexpr int NSTAGE      = 3;
static constexpr int SMEM_BYTES  = 1024 + NSTAGE * STAGE_BYTES; // 99328

// Compute NKK kk-steps of one chunk with fragment double-buffering.
#define COMPUTE_CHUNK(NKK)                                                          \
    do {                                                                            \
        uint32_t af[2][4][4], bf[2][2][4];                                          \
        _Pragma("unroll")                                                           \
        for (int mf = 0; mf < 4; mf++)                                              \
            ldsm_x4(af[0][mf][0], af[0][mf][1], af[0][mf][2], af[0][mf][3],         \
                    abase + pa[mf]);                                                \
        _Pragma("unroll")                                                           \
        for (int p = 0; p < 2; p++)                                                 \
            ldsm_x4(bf[0][p][0], bf[0][p][1], bf[0][p][2], bf[0][p][3],             \
                    bbase + pb[p]);                                                 \
        _Pragma("unroll")                                                           \
        for (int kk = 0; kk < (NKK); kk++) {                                        \
            const int cur = kk & 1, nxt = cur ^ 1;                                  \
            if (kk < (NKK) - 1) {                                                   \
                const uint32_t kx = (uint32_t)((kk + 1) * 32);                      \
                _Pragma("unroll")                                                   \
                for (int mf = 0; mf < 4; mf++)                                      \
                    ldsm_x4(af[nxt][mf][0], af[nxt][mf][1], af[nxt][mf][2],         \
                            af[nxt][mf][3], abase + (pa[mf] ^ kx));                 \
                _Pragma("unroll")                                                   \
                for (int p = 0; p < 2; p++)                                         \
                    ldsm_x4(bf[nxt][p][0], bf[nxt][p][1], bf[nxt][p][2],            \
                            bf[nxt][p][3], bbase + (pb[p] ^ kx));                   \
            }                                                                       \
            _Pragma("unroll")                                                       \
            for (int mf = 0; mf < 4; mf++) {                                        \
                _Pragma("unroll")                                                   \
                for (int p = 0; p < 2; p++) {                                       \
                    mma16816(acc[mf][2 * p], af[cur][mf][0], af[cur][mf][1],        \
                             af[cur][mf][2], af[cur][mf][3],                        \
                             bf[cur][p][0], bf[cur][p][2]);                         \
                    mma16816(acc[mf][2 * p + 1], af[cur][mf][0], af[cur][mf][1],    \
                             af[cur][mf][2], af[cur][mf][3],                        \
                             bf[cur][p][1], bf[cur][p][3]);                         \
                }                                                                   \
            }                                                                       \
        }                                                                           \
    } while (0)

__global__ __launch_bounds__(256, 2)
void gemm_bias_elu(const __nv_bfloat16* __restrict__ A, int lda, size_t a_es,
                   const __nv_bfloat16* __restrict__ Bw, int ldb, size_t b_es,
                   const float* __restrict__ bias, int bias_es,
                   __nv_bfloat16* __restrict__ C, int ldc, size_t c_es, int kchunks) {
    extern __shared__ unsigned char smem[];
    float* sbias = (float*)smem;
    unsigned char* tiles = smem + 1024;
    const uint32_t tiles_u = smem_u32(tiles);
    const int tid = threadIdx.x;
    const int e  = blockIdx.z;
    const int m0 = blockIdx.x * 128, n0 = blockIdx.y * 128;
    A    += (size_t)e * a_es;
    Bw   += (size_t)e * b_es;
    bias += (size_t)e * bias_es;
    C    += (size_t)e * c_es;

    if (tid < 128) sbias[tid] = bias[n0 + tid];

    // --- loader: each thread owns 4 consecutive 16B segs of one row per tile ---
    const int lr = tid >> 1;
    const uint32_t lbase = (tid & 1) * 64;
    const char* gA = (const char*)A + ((size_t)(m0 + lr) * lda) * 2 + lbase;
    const char* gB = (const char*)Bw + ((size_t)(n0 + lr) * ldb) * 2 + lbase;
    const uint32_t su   = (uint32_t)lr * 128 + lbase;
    const uint32_t sxor = (su >> 3) & 0x70;

    auto load_stage = [&](int s, int buf) {
        uint32_t ab = tiles_u + buf * STAGE_BYTES;
        uint32_t bb = ab + 16384;
        const char* a = gA + (size_t)s * 128;
        const char* b = gB + (size_t)s * 128;
#pragma unroll
        for (int i = 0; i < 4; i++) {
            uint32_t so = (su + i * 16) ^ sxor;
            cp16(ab + so, a + i * 16);
            cp16(bb + so, b + i * 16);
        }
        asm volatile("cp.async.commit_group;" ::: "memory");
    };

    load_stage(0, 0);
    load_stage(1, 1);

    const int lane = tid & 31, w = tid >> 5;
    const int wm = (w >> 2) * 64;
    const int wn = (w & 3) * 32;
    const int arow = lane & 15, ahalf = (lane >> 4) * 16;

    uint32_t pa[4], pb[2];
#pragma unroll
    for (int mf = 0; mf < 4; mf++)
        pa[mf] = swz128((uint32_t)((wm + mf * 16 + arow) * 128 + ahalf));
#pragma unroll
    for (int p = 0; p < 2; p++)
        pb[p] = swz128((uint32_t)((wn + p * 16 + arow) * 128 + ahalf));

    float acc[4][4][4];
#pragma unroll
    for (int mf = 0; mf < 4; mf++)
#pragma unroll
        for (int nf = 0; nf < 4; nf++)
#pragma unroll
            for (int i = 0; i < 4; i++) acc[mf][nf][i] = 0.f;

    int buf = 0, nbuf = 2;
    for (int s = 0; s < kchunks; s++) {
        asm volatile("cp.async.wait_group 1;" ::: "memory");
        __syncthreads();
        if (s + 2 < kchunks) load_stage(s + 2, nbuf);
        else asm volatile("cp.async.commit_group;" ::: "memory");

        uint32_t abase = tiles_u + buf * STAGE_BYTES;
        uint32_t bbase = abase + 16384;

        if (s < kchunks - 1) {
            COMPUTE_CHUNK(4);
        } else {
            COMPUTE_CHUNK(2);   // last chunk: real K ends 32 cols in; rest are zeros
        }
        buf = (buf == 2) ? 0 : buf + 1;
        nbuf = (nbuf == 2) ? 0 : nbuf + 1;
    }

    // ---- epilogue: bias + ELU + bf16 store ----
    const int cg = lane >> 2;
    const int cc = (lane & 3) * 2;
#pragma unroll
    for (int mf = 0; mf < 4; mf++) {
        int r0 = m0 + wm + mf * 16 + cg;
        int r1 = r0 + 8;
#pragma unroll
        for (int nf = 0; nf < 4; nf++) {
            int col = wn + nf * 8 + cc;
            float b0 = sbias[col], b1v = sbias[col + 1];
            float v0 = acc[mf][nf][0] + b0, v1 = acc[mf][nf][1] + b1v;
            float v2 = acc[mf][nf][2] + b0, v3 = acc[mf][nf][3] + b1v;
            v0 = v0 > 0.f ? v0 : (__expf(v0) - 1.f);
            v1 = v1 > 0.f ? v1 : (__expf(v1) - 1.f);
            v2 = v2 > 0.f ? v2 : (__expf(v2) - 1.f);
            v3 = v3 > 0.f ? v3 : (__expf(v3) - 1.f);
            *(__nv_bfloat162*)(C + (size_t)r0 * ldc + n0 + col) = __floats2bfloat162_rn(v0, v1);
            *(__nv_bfloat162*)(C + (size_t)r1 * ldc + n0 + col) = __floats2bfloat162_rn(v2, v3);
        }
    }
}

// ---------------- gate layer 3 (N=8) + deterministic partial norm ----------------
__global__ void gate3_kernel(const __nv_bfloat16* __restrict__ g2,
                             const float* __restrict__ gw3, const float* __restrict__ gb3,
                             float* __restrict__ para, float* __restrict__ partial) {
    __shared__ float sw[8 * 512];
    __shared__ float wsum[8];
    int tid = threadIdx.x;
    for (int i = tid; i < 4096; i += 256) { int k = i / 8, e = i % 8; sw[e * 512 + k] = gw3[k * 8 + e]; }
    __syncthreads();
    int warp = tid / 32, lane = tid % 32;
    int row = blockIdx.x * 8 + warp;
    float acc[8];
#pragma unroll
    for (int e = 0; e < 8; e++) acc[e] = 0.f;
    const __nv_bfloat162* gr = (const __nv_bfloat162*)(g2 + (size_t)row * KH);
#pragma unroll
    for (int i = 0; i < 8; i++) {
        __nv_bfloat162 p = gr[i * 32 + lane];
        float a0 = __bfloat162float(p.x), a1 = __bfloat162float(p.y);
        int k0 = i * 64 + lane * 2;
#pragma unroll
        for (int e = 0; e < 8; e++) acc[e] += a0 * sw[e * 512 + k0] + a1 * sw[e * 512 + k0 + 1];
    }
#pragma unroll
    for (int off = 16; off; off >>= 1)
#pragma unroll
        for (int e = 0; e < 8; e++) acc[e] += __shfl_down_sync(0xFFFFFFFFu, acc[e], off);
    if (lane == 0) {
        float ss = 0.f;
#pragma unroll
        for (int e = 0; e < 8; e++) {
            float v = acc[e] + gb3[e];
            v = v > 0.f ? v : (__expf(v) - 1.f);
            para[(size_t)row * 8 + e] = v;
            ss += v * v;
        }
        wsum[warp] = ss;
    }
    __syncthreads();
    if (tid == 0) {
        float s = 0.f;
        for (int w = 0; w < 8; w++) s += wsum[w];
        partial[blockIdx.x] = s;
    }
}

__global__ void reduce_norm_kernel(const float* __restrict__ partial, float* __restrict__ invnorm) {
    __shared__ float s[256];
    int tid = threadIdx.x;
    float v = 0.f;
    for (int k = 0; k < 8; k++) v += partial[tid + k * 256];
    s[tid] = v;
    __syncthreads();
    for (int off = 128; off; off >>= 1) {
        if (tid < off) s[tid] += s[tid + off];
        __syncthreads();
    }
    if (tid == 0) *invnorm = rsqrtf(s[0]);
}

// ---------------- combine ----------------
__global__ void combine_kernel(const float* __restrict__ para, const __nv_bfloat16* __restrict__ h3,
                               const float* __restrict__ invnorm, float* __restrict__ out) {
    int t = blockIdx.x * 256 + threadIdx.x;
    int b = t >> 7;
    float inv = *invnorm;
    float4 p0 = ((const float4*)para)[b * 2];
    float4 p1 = ((const float4*)para)[b * 2 + 1];
    float pe[8] = {p0.x, p0.y, p0.z, p0.w, p1.x, p1.y, p1.z, p1.w};
    float acc = 0.f;
#pragma unroll
    for (int e = 0; e < 8; e++)
        acc += pe[e] * __bfloat162float(h3[(size_t)e * B_ * M_OUT + t]);
    float x = acc * inv;
    out[t] = 1.f / (1.f + __expf(-x));
}

// ---------------- host launcher ----------------
extern "C" void kernel_launch(void* const* d_in, const int* in_sizes, int n_in,
                              void* d_out, int out_size) {
    const float* motions = (const float*)d_in[0];
    const float* z       = (const float*)d_in[1];
    const float* gw1     = (const float*)d_in[2];
    const float* gb1     = (const float*)d_in[3];
    const float* gw2     = (const float*)d_in[4];
    const float* gb2     = (const float*)d_in[5];
    const float* gw3     = (const float*)d_in[6];
    const float* gb3     = (const float*)d_in[7];
    const float* W1      = (const float*)d_in[8];
    const float* b1      = (const float*)d_in[9];
    const float* W2      = (const float*)d_in[10];
    const float* b2      = (const float*)d_in[11];
    const float* W3      = (const float*)d_in[12];
    const float* b3      = (const float*)d_in[13];
    float* out = (float*)d_out;

    unsigned char* sc = nullptr;
    cudaGetSymbolAddress((void**)&sc, g_scratch);
    __nv_bfloat16* xpad = (__nv_bfloat16*)(sc + OFF_XPAD);
    __nv_bfloat16* h1e  = (__nv_bfloat16*)(sc + OFF_H1);
    __nv_bfloat16* h2e  = (__nv_bfloat16*)(sc + OFF_H2);
    __nv_bfloat16* h3   = (__nv_bfloat16*)(sc + OFF_H3);
    float* para = (float*)(sc + OFF_PARA);
    float* part = (float*)(sc + OFF_PART);
    float* inv  = (float*)(sc + OFF_INV);
    __nv_bfloat16* W1t  = (__nv_bfloat16*)(sc + OFF_W1T);
    __nv_bfloat16* W2t  = (__nv_bfloat16*)(sc + OFF_W2T);
    __nv_bfloat16* W3t  = (__nv_bfloat16*)(sc + OFF_W3T);
    float* b1a = (float*)(sc + OFF_B1A);
    float* b2a = (float*)(sc + OFF_B2A);

    cudaFuncSetAttribute(gemm_bias_elu, cudaFuncAttributeMaxDynamicSharedMemorySize, SMEM_BYTES);

    const int PREP_T = B_ * (KX + 64);
    prep_kernel<<<(PREP_T + 255) / 256, 256>>>(motions, z, xpad, h1e, h2e);
    wconv_kernel<<<(WC_TOT + 255) / 256, 256>>>(gw1, gw2, W1, W2, W3, gb1, gb2, b1, b2,
                                                W1t, W2t, W3t, b1a, b2a);

    dim3 gL12(B_ / 128, 4, NS);   // 9 z-slices: experts 0..7 + gate
    dim3 gL3(B_ / 128, 1, NE);

    // Layer 1: out slot e of h1e (gate -> slot 8)
    gemm_bias_elu<<<gL12, 256, SMEM_BYTES>>>(xpad, KX, 0,
                                             W1t, KX, (size_t)H * KX,
                                             b1a, H,
                                             h1e, KH, (size_t)B_ * KH, KX / 64);
    // Layer 2
    gemm_bias_elu<<<gL12, 256, SMEM_BYTES>>>(h1e, KH, (size_t)B_ * KH,
                                             W2t, KH, (size_t)H * KH,
                                             b2a, H,
                                             h2e, KH, (size_t)B_ * KH, KH / 64);
    // gate layer 3 + norm (reads h2e slot 8)
    gate3_kernel<<<B_ / 8, 256>>>(h2e + (size_t)NE * B_ * KH, gw3, gb3, para, part);
    reduce_norm_kernel<<<1, 256>>>(part, inv);

    // Layer 3 (experts only)
    gemm_bias_elu<<<gL3, 256, SMEM_BYTES>>>(h2e, KH, (size_t)B_ * KH,
                                            W3t, KH, (size_t)M_OUT * KH,
                                            b3, M_OUT,
                                            h3, M_OUT, (size_t)B_ * M_OUT, KH / 64);

    combine_kernel<<<(B_ * M_OUT) / 256, 256>>>(para, h3, inv, out);
}

// round 11
// speedup vs baseline: 1.1570x; 1.0209x over previous
#include <cuda_runtime.h>
#include <cuda_bf16.h>
#include <stdint.h>

// ---------------- problem constants ----------------
static constexpr int B_    = 16384;
static constexpr int KX    = 320;   // padded input K storage (288 real)
static constexpr int KH    = 576;   // padded hidden K storage (544 real)
static constexpr int H     = 512;
static constexpr int M_OUT = 128;
static constexpr int NE    = 8;
static constexpr int NS    = NE + 1; // 8 experts + gate slot

// ---------------- scratch layout (single __device__ array) ----------------
static constexpr size_t OFF_XPAD = 0;
static constexpr size_t SZ_XPAD  = (size_t)B_*KX*2;
static constexpr size_t OFF_H1   = OFF_XPAD + SZ_XPAD;
static constexpr size_t SZ_HEXT  = (size_t)NS*B_*KH*2;      // 9 slots (slot 8 = gate)
static constexpr size_t OFF_H2   = OFF_H1 + SZ_HEXT;
static constexpr size_t OFF_H3   = OFF_H2 + SZ_HEXT;
static constexpr size_t SZ_H3    = (size_t)NE*B_*M_OUT*2;
static constexpr size_t OFF_PARA = OFF_H3 + SZ_H3;
static constexpr size_t SZ_PARA  = (size_t)B_*NE*4;
static constexpr size_t OFF_PART = OFF_PARA + SZ_PARA;
static constexpr size_t SZ_PART  = 2048*4;
static constexpr size_t OFF_INV  = OFF_PART + SZ_PART;
static constexpr size_t SZ_INV   = 256;
static constexpr size_t OFF_W1T  = OFF_INV + SZ_INV;
static constexpr size_t SZ_W1T   = (size_t)NS*H*KX*2;
static constexpr size_t OFF_W2T  = OFF_W1T + SZ_W1T;
static constexpr size_t SZ_W2T   = (size_t)NS*H*KH*2;
static constexpr size_t OFF_W3T  = OFF_W2T + SZ_W2T;
static constexpr size_t SZ_W3T   = (size_t)NE*M_OUT*KH*2;
static constexpr size_t OFF_B1A  = OFF_W3T + SZ_W3T;
static constexpr size_t SZ_B1A   = (size_t)NS*H*4;
static constexpr size_t OFF_B2A  = OFF_B1A + SZ_B1A;
static constexpr size_t SZ_B2A   = (size_t)NS*H*4;
static constexpr size_t SCRATCH_TOTAL = OFF_B2A + SZ_B2A;

__device__ __align__(1024) unsigned char g_scratch[SCRATCH_TOTAL];

// ---------------- helpers ----------------
__device__ __forceinline__ uint32_t smem_u32(const void* p) {
    return (uint32_t)__cvta_generic_to_shared(p);
}
__device__ __forceinline__ uint32_t swz128(uint32_t off) {
    return off ^ ((off >> 3) & 0x70);
}
__device__ __forceinline__ void cp16(uint32_t dst, const void* src) {
    asm volatile("cp.async.cg.shared.global [%0], [%1], 16;\n" :: "r"(dst), "l"(src) : "memory");
}
__device__ __forceinline__ void ldsm_x4(uint32_t& r0, uint32_t& r1, uint32_t& r2, uint32_t& r3,
                                        uint32_t addr) {
    asm volatile("ldmatrix.sync.aligned.m8n8.x4.shared.b16 {%0,%1,%2,%3}, [%4];"
                 : "=r"(r0), "=r"(r1), "=r"(r2), "=r"(r3) : "r"(addr));
}
__device__ __forceinline__ void mma16816(float* c, uint32_t a0, uint32_t a1, uint32_t a2, uint32_t a3,
                                         uint32_t b0, uint32_t b1) {
    asm volatile(
        "mma.sync.aligned.m16n8k16.row.col.f32.bf16.bf16.f32 "
        "{%0,%1,%2,%3}, {%4,%5,%6,%7}, {%8,%9}, {%0,%1,%2,%3};"
        : "+f"(c[0]), "+f"(c[1]), "+f"(c[2]), "+f"(c[3])
        : "r"(a0), "r"(a1), "r"(a2), "r"(a3), "r"(b0), "r"(b1));
}

// ---------------- unified setup kernel ----------------
// Segments of blockIdx.x:
//   [0, SEG0)            prep: xpad + z-columns of h1e/h2e expert slots
//   [SEG0, SEG1)         W1 transpose tiles  (NS slices x 10 ktiles x 16 ntiles)
//   [SEG1, SEG2)         W2 transpose tiles  (NS slices x 18 ktiles x 16 ntiles)
//   [SEG2, SEG3)         W3 transpose tiles  (NE slices x 18 ktiles x 4 ntiles)
//   [SEG3, SEG4)         bias arrays
static constexpr int PREP_BLK = (B_ * (KX + 64)) / 256;          // 24576
static constexpr int W1_TILES = NS * (KX / 32) * (H / 32);       // 9*10*16 = 1440
static constexpr int W2_TILES = NS * (KH / 32) * (H / 32);       // 9*18*16 = 2592
static constexpr int W3_TILES = NE * (KH / 32) * (M_OUT / 32);   // 8*18*4  = 576
static constexpr int BIAS_BLK = (2 * NS * H) / 256;              // 36
static constexpr int SEG0 = PREP_BLK;
static constexpr int SEG1 = SEG0 + W1_TILES;
static constexpr int SEG2 = SEG1 + W2_TILES;
static constexpr int SEG3 = SEG2 + W3_TILES;
static constexpr int SEG4 = SEG3 + BIAS_BLK;

__global__ void setup_kernel(const float* __restrict__ motions, const float* __restrict__ z,
                             const float* __restrict__ gw1, const float* __restrict__ gw2,
                             const float* __restrict__ W1, const float* __restrict__ W2,
                             const float* __restrict__ W3,
                             const float* __restrict__ gb1, const float* __restrict__ gb2,
                             const float* __restrict__ b1, const float* __restrict__ b2,
                             __nv_bfloat16* __restrict__ xpad,
                             __nv_bfloat16* __restrict__ h1e, __nv_bfloat16* __restrict__ h2e,
                             __nv_bfloat16* __restrict__ W1t, __nv_bfloat16* __restrict__ W2t,
                             __nv_bfloat16* __restrict__ W3t,
                             float* __restrict__ b1a, float* __restrict__ b2a) {
    const int bid = blockIdx.x;
    const int tid = threadIdx.x;

    if (bid < SEG0) {
        // ---- prep ----
        int idx = bid * 256 + tid;
        const int XT = B_ * KX;
        if (idx < XT) {
            int row = idx / KX, c = idx % KX;
            float v = 0.f;
            if (c < 256)      v = motions[(size_t)row * 256 + c];
            else if (c < 288) v = z[(size_t)row * 32 + (c - 256)];
            xpad[idx] = __float2bfloat16(v);
        } else {
            int j = idx - XT;                 // < B_*64
            int row = j / 64, c = j % 64;
            __nv_bfloat16 v = __float2bfloat16(c < 32 ? z[(size_t)row * 32 + c] : 0.f);
            size_t base = (size_t)row * KH + 512 + c;
#pragma unroll
            for (int e = 0; e < NE; e++) {
                h1e[(size_t)e * B_ * KH + base] = v;
                h2e[(size_t)e * B_ * KH + base] = v;
            }
        }
        return;
    }

    if (bid < SEG3) {
        // ---- coalesced weight transpose via 32x33 smem tile ----
        __shared__ float sm[32][33];
        int kdim, slice, k0, n0;               // source: SRC[k][n], dest: DST[n*kdim + k]
        const float* src = nullptr;            // row stride = ncols of source
        int src_ncols, kreal;
        __nv_bfloat16* dst;
        size_t dst_slice_off;

        if (bid < SEG1) {
            int b = bid - SEG0;
            slice = b / ((KX / 32) * (H / 32));
            int r = b % ((KX / 32) * (H / 32));
            k0 = (r / (H / 32)) * 32; n0 = (r % (H / 32)) * 32;
            kdim = KX; src_ncols = H; kreal = 288;
            src = (slice < NE) ? (W1 + (size_t)slice * 288 * H) : gw1;
            dst = W1t; dst_slice_off = (size_t)slice * H * KX;
        } else if (bid < SEG2) {
            int b = bid - SEG1;
            slice = b / ((KH / 32) * (H / 32));
            int r = b % ((KH / 32) * (H / 32));
            k0 = (r / (H / 32)) * 32; n0 = (r % (H / 32)) * 32;
            kdim = KH; src_ncols = H; kreal = (slice < NE) ? 544 : 512;
            src = (slice < NE) ? (W2 + (size_t)slice * 544 * H) : gw2;
            dst = W2t; dst_slice_off = (size_t)slice * H * KH;
        } else {
            int b = bid - SEG2;
            slice = b / ((KH / 32) * (M_OUT / 32));
            int r = b % ((KH / 32) * (M_OUT / 32));
            k0 = (r / (M_OUT / 32)) * 32; n0 = (r % (M_OUT / 32)) * 32;
            kdim = KH; src_ncols = M_OUT; kreal = 544;
            src = W3 + (size_t)slice * 544 * M_OUT;
            dst = W3t; dst_slice_off = (size_t)slice * M_OUT * KH;
        }

        // load (coalesced along n)
        {
            int nn = tid & 31, row = tid >> 5;
#pragma unroll
            for (int i = 0; i < 4; i++) {
                int kk = row + i * 8;
                int k = k0 + kk;
                sm[kk][nn] = (k < kreal) ? src[(size_t)k * src_ncols + (n0 + nn)] : 0.f;
            }
        }
        __syncthreads();
        // store (coalesced along k)
        {
            int kk = tid & 31, row = tid >> 5;
#pragma unroll
            for (int i = 0; i < 4; i++) {
                int nr = row + i * 8;
                dst[dst_slice_off + (size_t)(n0 + nr) * kdim + (k0 + kk)] =
                    __float2bfloat16(sm[kk][nr]);
            }
        }
        return;
    }

    // ---- bias arrays ----
    {
        int idx = (bid - SEG3) * 256 + tid;    // < 2*NS*H
        const int T = NS * H;
        if (idx < T) {
            int e = idx / H, n = idx % H;
            b1a[idx] = (e < NE) ? b1[(size_t)e * H + n] : gb1[n];
        } else {
            idx -= T;
            int e = idx / H, n = idx % H;
            b2a[idx] = (e < NE) ? b2[(size_t)e * H + n] : gb2[n];
        }
    }
}

// ---------------- HMMA GEMM: C[m,n] = elu(sum_k A[m,k]*Bt[n,k] + bias[n]) -> bf16 ----------------
// R9 WIN config (unchanged): 256 threads, tile 128x128, K-chunks of 64, 3-stage cp.async
// ring, 2 CTAs/SM, warps 2(M)x4(N), warp tile 64x32, fragment double-buffer.
// Last chunk computes only 2 of 4 kk-steps (real K ends 32 cols in; rest exact zeros).
static constexpr int STAGE_BYTES = 16384 + 16384;
static constexpr int NSTAGE      = 3;
static constexpr int SMEM_BYTES  = 1024 + NSTAGE * STAGE_BYTES; // 99328

#define COMPUTE_CHUNK(NKK)                                                          \
    do {                                                                            \
        uint32_t af[2][4][4], bf[2][2][4];                                          \
        _Pragma("unroll")                                                           \
        for (int mf = 0; mf < 4; mf++)                                              \
            ldsm_x4(af[0][mf][0], af[0][mf][1], af[0][mf][2], af[0][mf][3],         \
                    abase + pa[mf]);                                                \
        _Pragma("unroll")                                                           \
        for (int p = 0; p < 2; p++)                                                 \
            ldsm_x4(bf[0][p][0], bf[0][p][1], bf[0][p][2], bf[0][p][3],             \
                    bbase + pb[p]);                                                 \
        _Pragma("unroll")                                                           \
        for (int kk = 0; kk < (NKK); kk++) {                                        \
            const int cur = kk & 1, nxt = cur ^ 1;                                  \
            if (kk < (NKK) - 1) {                                                   \
                const uint32_t kx = (uint32_t)((kk + 1) * 32);                      \
                _Pragma("unroll")                                                   \
                for (int mf = 0; mf < 4; mf++)                                      \
                    ldsm_x4(af[nxt][mf][0], af[nxt][mf][1], af[nxt][mf][2],         \
                            af[nxt][mf][3], abase + (pa[mf] ^ kx));                 \
                _Pragma("unroll")                                                   \
                for (int p = 0; p < 2; p++)                                         \
                    ldsm_x4(bf[nxt][p][0], bf[nxt][p][1], bf[nxt][p][2],            \
                            bf[nxt][p][3], bbase + (pb[p] ^ kx));                   \
            }                                                                       \
            _Pragma("unroll")                                                       \
            for (int mf = 0; mf < 4; mf++) {                                        \
                _Pragma("unroll")                                                   \
                for (int p = 0; p < 2; p++) {                                       \
                    mma16816(acc[mf][2 * p], af[cur][mf][0], af[cur][mf][1],        \
                             af[cur][mf][2], af[cur][mf][3],                        \
                             bf[cur][p][0], bf[cur][p][2]);                         \
                    mma16816(acc[mf][2 * p + 1], af[cur][mf][0], af[cur][mf][1],    \
                             af[cur][mf][2], af[cur][mf][3],                        \
                             bf[cur][p][1], bf[cur][p][3]);                         \
                }                                                                   \
            }                                                                       \
        }                                                                           \
    } while (0)

__global__ __launch_bounds__(256, 2)
void gemm_bias_elu(const __nv_bfloat16* __restrict__ A, int lda, size_t a_es,
                   const __nv_bfloat16* __restrict__ Bw, int ldb, size_t b_es,
                   const float* __restrict__ bias, int bias_es,
                   __nv_bfloat16* __restrict__ C, int ldc, size_t c_es, int kchunks) {
    extern __shared__ unsigned char smem[];
    float* sbias = (float*)smem;
    unsigned char* tiles = smem + 1024;
    const uint32_t tiles_u = smem_u32(tiles);
    const int tid = threadIdx.x;
    const int e  = blockIdx.z;
    const int m0 = blockIdx.x * 128, n0 = blockIdx.y * 128;
    A    += (size_t)e * a_es;
    Bw   += (size_t)e * b_es;
    bias += (size_t)e * bias_es;
    C    += (size_t)e * c_es;

    if (tid < 128) sbias[tid] = bias[n0 + tid];

    const int lr = tid >> 1;
    const uint32_t lbase = (tid & 1) * 64;
    const char* gA = (const char*)A + ((size_t)(m0 + lr) * lda) * 2 + lbase;
    const char* gB = (const char*)Bw + ((size_t)(n0 + lr) * ldb) * 2 + lbase;
    const uint32_t su   = (uint32_t)lr * 128 + lbase;
    const uint32_t sxor = (su >> 3) & 0x70;

    auto load_stage = [&](int s, int buf) {
        uint32_t ab = tiles_u + buf * STAGE_BYTES;
        uint32_t bb = ab + 16384;
        const char* a = gA + (size_t)s * 128;
        const char* b = gB + (size_t)s * 128;
#pragma unroll
        for (int i = 0; i < 4; i++) {
            uint32_t so = (su + i * 16) ^ sxor;
            cp16(ab + so, a + i * 16);
            cp16(bb + so, b + i * 16);
        }
        asm volatile("cp.async.commit_group;" ::: "memory");
    };

    load_stage(0, 0);
    load_stage(1, 1);

    const int lane = tid & 31, w = tid >> 5;
    const int wm = (w >> 2) * 64;
    const int wn = (w & 3) * 32;
    const int arow = lane & 15, ahalf = (lane >> 4) * 16;

    uint32_t pa[4], pb[2];
#pragma unroll
    for (int mf = 0; mf < 4; mf++)
        pa[mf] = swz128((uint32_t)((wm + mf * 16 + arow) * 128 + ahalf));
#pragma unroll
    for (int p = 0; p < 2; p++)
        pb[p] = swz128((uint32_t)((wn + p * 16 + arow) * 128 + ahalf));

    float acc[4][4][4];
#pragma unroll
    for (int mf = 0; mf < 4; mf++)
#pragma unroll
        for (int nf = 0; nf < 4; nf++)
#pragma unroll
            for (int i = 0; i < 4; i++) acc[mf][nf][i] = 0.f;

    int buf = 0, nbuf = 2;
    for (int s = 0; s < kchunks; s++) {
        asm volatile("cp.async.wait_group 1;" ::: "memory");
        __syncthreads();
        if (s + 2 < kchunks) load_stage(s + 2, nbuf);
        else asm volatile("cp.async.commit_group;" ::: "memory");

        uint32_t abase = tiles_u + buf * STAGE_BYTES;
        uint32_t bbase = abase + 16384;

        if (s < kchunks - 1) {
            COMPUTE_CHUNK(4);
        } else {
            COMPUTE_CHUNK(2);
        }
        buf = (buf == 2) ? 0 : buf + 1;
        nbuf = (nbuf == 2) ? 0 : nbuf + 1;
    }

    const int cg = lane >> 2;
    const int cc = (lane & 3) * 2;
#pragma unroll
    for (int mf = 0; mf < 4; mf++) {
        int r0 = m0 + wm + mf * 16 + cg;
        int r1 = r0 + 8;
#pragma unroll
        for (int nf = 0; nf < 4; nf++) {
            int col = wn + nf * 8 + cc;
            float b0 = sbias[col], b1v = sbias[col + 1];
            float v0 = acc[mf][nf][0] + b0, v1 = acc[mf][nf][1] + b1v;
            float v2 = acc[mf][nf][2] + b0, v3 = acc[mf][nf][3] + b1v;
            v0 = v0 > 0.f ? v0 : (__expf(v0) - 1.f);
            v1 = v1 > 0.f ? v1 : (__expf(v1) - 1.f);
            v2 = v2 > 0.f ? v2 : (__expf(v2) - 1.f);
            v3 = v3 > 0.f ? v3 : (__expf(v3) - 1.f);
            *(__nv_bfloat162*)(C + (size_t)r0 * ldc + n0 + col) = __floats2bfloat162_rn(v0, v1);
            *(__nv_bfloat162*)(C + (size_t)r1 * ldc + n0 + col) = __floats2bfloat162_rn(v2, v3);
        }
    }
}

// ---------------- gate layer 3 (N=8) + deterministic partial norm ----------------
__global__ void gate3_kernel(const __nv_bfloat16* __restrict__ g2,
                             const float* __restrict__ gw3, const float* __restrict__ gb3,
                             float* __restrict__ para, float* __restrict__ partial) {
    __shared__ float sw[8 * 512];
    __shared__ float wsum[8];
    int tid = threadIdx.x;
    for (int i = tid; i < 4096; i += 256) { int k = i / 8, e = i % 8; sw[e * 512 + k] = gw3[k * 8 + e]; }
    __syncthreads();
    int warp = tid / 32, lane = tid % 32;
    int row = blockIdx.x * 8 + warp;
    float acc[8];
#pragma unroll
    for (int e = 0; e < 8; e++) acc[e] = 0.f;
    const __nv_bfloat162* gr = (const __nv_bfloat162*)(g2 + (size_t)row * KH);
#pragma unroll
    for (int i = 0; i < 8; i++) {
        __nv_bfloat162 p = gr[i * 32 + lane];
        float a0 = __bfloat162float(p.x), a1 = __bfloat162float(p.y);
        int k0 = i * 64 + lane * 2;
#pragma unroll
        for (int e = 0; e < 8; e++) acc[e] += a0 * sw[e * 512 + k0] + a1 * sw[e * 512 + k0 + 1];
    }
#pragma unroll
    for (int off = 16; off; off >>= 1)
#pragma unroll
        for (int e = 0; e < 8; e++) acc[e] += __shfl_down_sync(0xFFFFFFFFu, acc[e], off);
    if (lane == 0) {
        float ss = 0.f;
#pragma unroll
        for (int e = 0; e < 8; e++) {
            float v = acc[e] + gb3[e];
            v = v > 0.f ? v : (__expf(v) - 1.f);
            para[(size_t)row * 8 + e] = v;
            ss += v * v;
        }
        wsum[warp] = ss;
    }
    __syncthreads();
    if (tid == 0) {
        float s = 0.f;
        for (int w = 0; w < 8; w++) s += wsum[w];
        partial[blockIdx.x] = s;
    }
}

__global__ void reduce_norm_kernel(const float* __restrict__ partial, float* __restrict__ invnorm) {
    __shared__ float s[256];
    int tid = threadIdx.x;
    float v = 0.f;
    for (int k = 0; k < 8; k++) v += partial[tid + k * 256];
    s[tid] = v;
    __syncthreads();
    for (int off = 128; off; off >>= 1) {
        if (tid < off) s[tid] += s[tid + off];
        __syncthreads();
    }
    if (tid == 0) *invnorm = rsqrtf(s[0]);
}

// ---------------- combine ----------------
__global__ void combine_kernel(const float* __restrict__ para, const __nv_bfloat16* __restrict__ h3,
                               const float* __restrict__ invnorm, float* __restrict__ out) {
    int t = blockIdx.x * 256 + threadIdx.x;
    int b = t >> 7;
    float inv = *invnorm;
    float4 p0 = ((const float4*)para)[b * 2];
    float4 p1 = ((const float4*)para)[b * 2 + 1];
    float pe[8] = {p0.x, p0.y, p0.z, p0.w, p1.x, p1.y, p1.z, p1.w};
    float acc = 0.f;
#pragma unroll
    for (int e = 0; e < 8; e++)
        acc += pe[e] * __bfloat162float(h3[(size_t)e * B_ * M_OUT + t]);
    float x = acc * inv;
    out[t] = 1.f / (1.f + __expf(-x));
}

// ---------------- host launcher ----------------
extern "C" void kernel_launch(void* const* d_in, const int* in_sizes, int n_in,
                              void* d_out, int out_size) {
    const float* motions = (const float*)d_in[0];
    const float* z       = (const float*)d_in[1];
    const float* gw1     = (const float*)d_in[2];
    const float* gb1     = (const float*)d_in[3];
    const float* gw2     = (const float*)d_in[4];
    const float* gb2     = (const float*)d_in[5];
    const float* gw3     = (const float*)d_in[6];
    const float* gb3     = (const float*)d_in[7];
    const float* W1      = (const float*)d_in[8];
    const float* b1      = (const float*)d_in[9];
    const float* W2      = (const float*)d_in[10];
    const float* b2      = (const float*)d_in[11];
    const float* W3      = (const float*)d_in[12];
    const float* b3      = (const float*)d_in[13];
    float* out = (float*)d_out;

    unsigned char* sc = nullptr;
    cudaGetSymbolAddress((void**)&sc, g_scratch);
    __nv_bfloat16* xpad = (__nv_bfloat16*)(sc + OFF_XPAD);
    __nv_bfloat16* h1e  = (__nv_bfloat16*)(sc + OFF_H1);
    __nv_bfloat16* h2e  = (__nv_bfloat16*)(sc + OFF_H2);
    __nv_bfloat16* h3   = (__nv_bfloat16*)(sc + OFF_H3);
    float* para = (float*)(sc + OFF_PARA);
    float* part = (float*)(sc + OFF_PART);
    float* inv  = (float*)(sc + OFF_INV);
    __nv_bfloat16* W1t  = (__nv_bfloat16*)(sc + OFF_W1T);
    __nv_bfloat16* W2t  = (__nv_bfloat16*)(sc + OFF_W2T);
    __nv_bfloat16* W3t  = (__nv_bfloat16*)(sc + OFF_W3T);
    float* b1a = (float*)(sc + OFF_B1A);
    float* b2a = (float*)(sc + OFF_B2A);

    cudaFuncSetAttribute(gemm_bias_elu, cudaFuncAttributeMaxDynamicSharedMemorySize, SMEM_BYTES);

    // one fused setup launch: prep + coalesced weight transposes + bias arrays
    setup_kernel<<<SEG4, 256>>>(motions, z, gw1, gw2, W1, W2, W3, gb1, gb2, b1, b2,
                                xpad, h1e, h2e, W1t, W2t, W3t, b1a, b2a);

    dim3 gL12(B_ / 128, 4, NS);   // 9 z-slices: experts 0..7 + gate
    dim3 gL3(B_ / 128, 1, NE);

    // Layer 1: out slot e of h1e (gate -> slot 8)
    gemm_bias_elu<<<gL12, 256, SMEM_BYTES>>>(xpad, KX, 0,
                                             W1t, KX, (size_t)H * KX,
                                             b1a, H,
                                             h1e, KH, (size_t)B_ * KH, KX / 64);
    // Layer 2
    gemm_bias_elu<<<gL12, 256, SMEM_BYTES>>>(h1e, KH, (size_t)B_ * KH,
                                             W2t, KH, (size_t)H * KH,
                                             b2a, H,
                                             h2e, KH, (size_t)B_ * KH, KH / 64);
    // gate layer 3 + norm (reads h2e slot 8)
    gate3_kernel<<<B_ / 8, 256>>>(h2e + (size_t)NE * B_ * KH, gw3, gb3, para, part);
    reduce_norm_kernel<<<1, 256>>>(part, inv);

    // Layer 3 (experts only)
    gemm_bias_elu<<<gL3, 256, SMEM_BYTES>>>(h2e, KH, (size_t)B_ * KH,
                                            W3t, KH, (size_t)M_OUT * KH,
                                            b3, M_OUT,
                                            h3, M_OUT, (size_t)B_ * M_OUT, KH / 64);

    combine_kernel<<<(B_ * M_OUT) / 256, 256>>>(para, h3, inv, out);
}

// round 12
// speedup vs baseline: 1.1723x; 1.0132x over previous
#include <cuda_runtime.h>
#include <cuda_bf16.h>
#include <stdint.h>

// ---------------- problem constants ----------------
static constexpr int B_    = 16384;
static constexpr int KX    = 320;   // padded input K storage (288 real)
static constexpr int KH    = 576;   // padded hidden K storage (544 real)
static constexpr int H     = 512;
static constexpr int M_OUT = 128;
static constexpr int NE    = 8;
static constexpr int NS    = NE + 1; // 8 experts + gate slot

// ---------------- scratch layout (single __device__ array) ----------------
static constexpr size_t OFF_XPAD = 0;
static constexpr size_t SZ_XPAD  = (size_t)B_*KX*2;
static constexpr size_t OFF_H1   = OFF_XPAD + SZ_XPAD;
static constexpr size_t SZ_HEXT  = (size_t)NS*B_*KH*2;      // 9 slots (slot 8 = gate)
static constexpr size_t OFF_H2   = OFF_H1 + SZ_HEXT;
static constexpr size_t OFF_H3   = OFF_H2 + SZ_HEXT;
static constexpr size_t SZ_H3    = (size_t)NS*B_*M_OUT*2;   // slot 8 = para (gate L3 out)
static constexpr size_t OFF_PART = OFF_H3 + SZ_H3;
static constexpr size_t SZ_PART  = 2048*4;
static constexpr size_t OFF_INV  = OFF_PART + SZ_PART;
static constexpr size_t SZ_INV   = 256;
static constexpr size_t OFF_W1T  = OFF_INV + SZ_INV;
static constexpr size_t SZ_W1T   = (size_t)NS*H*KX*2;
static constexpr size_t OFF_W2T  = OFF_W1T + SZ_W1T;
static constexpr size_t SZ_W2T   = (size_t)NS*H*KH*2;
static constexpr size_t OFF_W3T  = OFF_W2T + SZ_W2T;
static constexpr size_t SZ_W3T   = (size_t)NS*M_OUT*KH*2;   // slice 8 = padded gw3^T
static constexpr size_t OFF_B1A  = OFF_W3T + SZ_W3T;
static constexpr size_t SZ_B1A   = (size_t)NS*H*4;
static constexpr size_t OFF_B2A  = OFF_B1A + SZ_B1A;
static constexpr size_t SZ_B2A   = (size_t)NS*H*4;
static constexpr size_t OFF_B3A  = OFF_B2A + SZ_B2A;
static constexpr size_t SZ_B3A   = (size_t)NS*M_OUT*4;
static constexpr size_t SCRATCH_TOTAL = OFF_B3A + SZ_B3A;

__device__ __align__(1024) unsigned char g_scratch[SCRATCH_TOTAL];

// ---------------- helpers ----------------
__device__ __forceinline__ uint32_t smem_u32(const void* p) {
    return (uint32_t)__cvta_generic_to_shared(p);
}
__device__ __forceinline__ uint32_t swz128(uint32_t off) {
    return off ^ ((off >> 3) & 0x70);
}
__device__ __forceinline__ void cp16(uint32_t dst, const void* src) {
    asm volatile("cp.async.cg.shared.global [%0], [%1], 16;\n" :: "r"(dst), "l"(src) : "memory");
}
__device__ __forceinline__ void ldsm_x4(uint32_t& r0, uint32_t& r1, uint32_t& r2, uint32_t& r3,
                                        uint32_t addr) {
    asm volatile("ldmatrix.sync.aligned.m8n8.x4.shared.b16 {%0,%1,%2,%3}, [%4];"
                 : "=r"(r0), "=r"(r1), "=r"(r2), "=r"(r3) : "r"(addr));
}
__device__ __forceinline__ void mma16816(float* c, uint32_t a0, uint32_t a1, uint32_t a2, uint32_t a3,
                                         uint32_t b0, uint32_t b1) {
    asm volatile(
        "mma.sync.aligned.m16n8k16.row.col.f32.bf16.bf16.f32 "
        "{%0,%1,%2,%3}, {%4,%5,%6,%7}, {%8,%9}, {%0,%1,%2,%3};"
        : "+f"(c[0]), "+f"(c[1]), "+f"(c[2]), "+f"(c[3])
        : "r"(a0), "r"(a1), "r"(a2), "r"(a3), "r"(b0), "r"(b1));
}

// ---------------- unified setup kernel ----------------
// Segments of blockIdx.x:
//   [0, SEG0)     prep: xpad + z-columns of h1e/h2e expert slots
//   [SEG0, SEG1)  W1 transpose tiles  (NS x 10 x 16)
//   [SEG1, SEG2)  W2 transpose tiles  (NS x 18 x 16)
//   [SEG2, SEG3)  W3 transpose tiles  (NS x 18 x 4; slice 8 = gw3 padded)
//   [SEG3, SEG4)  bias arrays (b1a, b2a, b3a)
static constexpr int PREP_BLK = (B_ * (KX + 64)) / 256;          // 24576
static constexpr int W1_TILES = NS * (KX / 32) * (H / 32);       // 1440
static constexpr int W2_TILES = NS * (KH / 32) * (H / 32);       // 2592
static constexpr int W3_TILES = NS * (KH / 32) * (M_OUT / 32);   // 9*18*4 = 648
static constexpr int BIAS_TOT = 2 * NS * H + NS * M_OUT;         // 10368
static constexpr int BIAS_BLK = (BIAS_TOT + 255) / 256;          // 41
static constexpr int SEG0 = PREP_BLK;
static constexpr int SEG1 = SEG0 + W1_TILES;
static constexpr int SEG2 = SEG1 + W2_TILES;
static constexpr int SEG3 = SEG2 + W3_TILES;
static constexpr int SEG4 = SEG3 + BIAS_BLK;

__global__ void setup_kernel(const float* __restrict__ motions, const float* __restrict__ z,
                             const float* __restrict__ gw1, const float* __restrict__ gw2,
                             const float* __restrict__ gw3,
                             const float* __restrict__ W1, const float* __restrict__ W2,
                             const float* __restrict__ W3,
                             const float* __restrict__ gb1, const float* __restrict__ gb2,
                             const float* __restrict__ gb3,
                             const float* __restrict__ b1, const float* __restrict__ b2,
                             const float* __restrict__ b3,
                             __nv_bfloat16* __restrict__ xpad,
                             __nv_bfloat16* __restrict__ h1e, __nv_bfloat16* __restrict__ h2e,
                             __nv_bfloat16* __restrict__ W1t, __nv_bfloat16* __restrict__ W2t,
                             __nv_bfloat16* __restrict__ W3t,
                             float* __restrict__ b1a, float* __restrict__ b2a,
                             float* __restrict__ b3a) {
    const int bid = blockIdx.x;
    const int tid = threadIdx.x;

    if (bid < SEG0) {
        // ---- prep ----
        int idx = bid * 256 + tid;
        const int XT = B_ * KX;
        if (idx < XT) {
            int row = idx / KX, c = idx % KX;
            float v = 0.f;
            if (c < 256)      v = motions[(size_t)row * 256 + c];
            else if (c < 288) v = z[(size_t)row * 32 + (c - 256)];
            xpad[idx] = __float2bfloat16(v);
        } else {
            int j = idx - XT;                 // < B_*64
            int row = j / 64, c = j % 64;
            __nv_bfloat16 v = __float2bfloat16(c < 32 ? z[(size_t)row * 32 + c] : 0.f);
            size_t base = (size_t)row * KH + 512 + c;
#pragma unroll
            for (int e = 0; e < NE; e++) {
                h1e[(size_t)e * B_ * KH + base] = v;
                h2e[(size_t)e * B_ * KH + base] = v;
            }
        }
        return;
    }

    if (bid < SEG3) {
        // ---- coalesced weight transpose via 32x33 smem tile ----
        __shared__ float sm[32][33];
        int kdim, slice, k0, n0;               // source: SRC[k][n], dest: DST[n*kdim + k]
        const float* src = nullptr;
        int src_ncols, kreal, nreal;
        __nv_bfloat16* dst;
        size_t dst_slice_off;

        if (bid < SEG1) {
            int b = bid - SEG0;
            slice = b / ((KX / 32) * (H / 32));
            int r = b % ((KX / 32) * (H / 32));
            k0 = (r / (H / 32)) * 32; n0 = (r % (H / 32)) * 32;
            kdim = KX; src_ncols = H; kreal = 288; nreal = H;
            src = (slice < NE) ? (W1 + (size_t)slice * 288 * H) : gw1;
            dst = W1t; dst_slice_off = (size_t)slice * H * KX;
        } else if (bid < SEG2) {
            int b = bid - SEG1;
            slice = b / ((KH / 32) * (H / 32));
            int r = b % ((KH / 32) * (H / 32));
            k0 = (r / (H / 32)) * 32; n0 = (r % (H / 32)) * 32;
            kdim = KH; src_ncols = H; nreal = H;
            kreal = (slice < NE) ? 544 : 512;
            src = (slice < NE) ? (W2 + (size_t)slice * 544 * H) : gw2;
            dst = W2t; dst_slice_off = (size_t)slice * H * KH;
        } else {
            int b = bid - SEG2;
            slice = b / ((KH / 32) * (M_OUT / 32));
            int r = b % ((KH / 32) * (M_OUT / 32));
            k0 = (r / (M_OUT / 32)) * 32; n0 = (r % (M_OUT / 32)) * 32;
            kdim = KH;
            if (slice < NE) {
                src = W3 + (size_t)slice * 544 * M_OUT;
                src_ncols = M_OUT; kreal = 544; nreal = M_OUT;
            } else {
                src = gw3;                     // [512, 8]
                src_ncols = 8; kreal = 512; nreal = 8;
            }
            dst = W3t; dst_slice_off = (size_t)slice * M_OUT * KH;
        }

        // load (coalesced along n)
        {
            int nn = tid & 31, row = tid >> 5;
#pragma unroll
            for (int i = 0; i < 4; i++) {
                int kk = row + i * 8;
                int k = k0 + kk;
                int n = n0 + nn;
                sm[kk][nn] = (k < kreal && n < nreal) ? src[(size_t)k * src_ncols + n] : 0.f;
            }
        }
        __syncthreads();
        // store (coalesced along k)
        {
            int kk = tid & 31, row = tid >> 5;
#pragma unroll
            for (int i = 0; i < 4; i++) {
                int nr = row + i * 8;
                dst[dst_slice_off + (size_t)(n0 + nr) * kdim + (k0 + kk)] =
                    __float2bfloat16(sm[kk][nr]);
            }
        }
        return;
    }

    // ---- bias arrays ----
    {
        int idx = (bid - SEG3) * 256 + tid;
        const int T12 = NS * H;
        if (idx < T12) {
            int e = idx / H, n = idx % H;
            b1a[idx] = (e < NE) ? b1[(size_t)e * H + n] : gb1[n];
        } else if (idx < 2 * T12) {
            idx -= T12;
            int e = idx / H, n = idx % H;
            b2a[idx] = (e < NE) ? b2[(size_t)e * H + n] : gb2[n];
        } else if (idx < BIAS_TOT) {
            idx -= 2 * T12;
            int e = idx / M_OUT, n = idx % M_OUT;
            b3a[idx] = (e < NE) ? b3[(size_t)e * M_OUT + n] : (n < 8 ? gb3[n] : 0.f);
        }
    }
}

// ---------------- HMMA GEMM: C[m,n] = elu(sum_k A[m,k]*Bt[n,k] + bias[n]) -> bf16 ----------------
// R9 WIN config (unchanged): 256 threads, tile 128x128, K-chunks of 64, 3-stage cp.async
// ring, 2 CTAs/SM, warps 2(M)x4(N), warp tile 64x32, fragment double-buffer.
// Last chunk computes only 2 of 4 kk-steps (real K ends <=32 cols in; rest exact zeros).
static constexpr int STAGE_BYTES = 16384 + 16384;
static constexpr int NSTAGE      = 3;
static constexpr int SMEM_BYTES  = 1024 + NSTAGE * STAGE_BYTES; // 99328

#define COMPUTE_CHUNK(NKK)                                                          \
    do {                                                                            \
        uint32_t af[2][4][4], bf[2][2][4];                                          \
        _Pragma("unroll")                                                           \
        for (int mf = 0; mf < 4; mf++)                                              \
            ldsm_x4(af[0][mf][0], af[0][mf][1], af[0][mf][2], af[0][mf][3],         \
                    abase + pa[mf]);                                                \
        _Pragma("unroll")                                                           \
        for (int p = 0; p < 2; p++)                                                 \
            ldsm_x4(bf[0][p][0], bf[0][p][1], bf[0][p][2], bf[0][p][3],             \
                    bbase + pb[p]);                                                 \
        _Pragma("unroll")                                                           \
        for (int kk = 0; kk < (NKK); kk++) {                                        \
            const int cur = kk & 1, nxt = cur ^ 1;                                  \
            if (kk < (NKK) - 1) {                                                   \
                const uint32_t kx = (uint32_t)((kk + 1) * 32);                      \
                _Pragma("unroll")                                                   \
                for (int mf = 0; mf < 4; mf++)                                      \
                    ldsm_x4(af[nxt][mf][0], af[nxt][mf][1], af[nxt][mf][2],         \
                            af[nxt][mf][3], abase + (pa[mf] ^ kx));                 \
                _Pragma("unroll")                                                   \
                for (int p = 0; p < 2; p++)                                         \
                    ldsm_x4(bf[nxt][p][0], bf[nxt][p][1], bf[nxt][p][2],            \
                            bf[nxt][p][3], bbase + (pb[p] ^ kx));                   \
            }                                                                       \
            _Pragma("unroll")                                                       \
            for (int mf = 0; mf < 4; mf++) {                                        \
                _Pragma("unroll")                                                   \
                for (int p = 0; p < 2; p++) {                                       \
                    mma16816(acc[mf][2 * p], af[cur][mf][0], af[cur][mf][1],        \
                             af[cur][mf][2], af[cur][mf][3],                        \
                             bf[cur][p][0], bf[cur][p][2]);                         \
                    mma16816(acc[mf][2 * p + 1], af[cur][mf][0], af[cur][mf][1],    \
                             af[cur][mf][2], af[cur][mf][3],                        \
                             bf[cur][p][1], bf[cur][p][3]);                         \
                }                                                                   \
            }                                                                       \
        }                                                                           \
    } while (0)

__global__ __launch_bounds__(256, 2)
void gemm_bias_elu(const __nv_bfloat16* __restrict__ A, int lda, size_t a_es,
                   const __nv_bfloat16* __restrict__ Bw, int ldb, size_t b_es,
                   const float* __restrict__ bias, int bias_es,
                   __nv_bfloat16* __restrict__ C, int ldc, size_t c_es, int kchunks) {
    extern __shared__ unsigned char smem[];
    float* sbias = (float*)smem;
    unsigned char* tiles = smem + 1024;
    const uint32_t tiles_u = smem_u32(tiles);
    const int tid = threadIdx.x;
    const int e  = blockIdx.z;
    const int m0 = blockIdx.x * 128, n0 = blockIdx.y * 128;
    A    += (size_t)e * a_es;
    Bw   += (size_t)e * b_es;
    bias += (size_t)e * bias_es;
    C    += (size_t)e * c_es;

    if (tid < 128) sbias[tid] = bias[n0 + tid];

    const int lr = tid >> 1;
    const uint32_t lbase = (tid & 1) * 64;
    const char* gA = (const char*)A + ((size_t)(m0 + lr) * lda) * 2 + lbase;
    const char* gB = (const char*)Bw + ((size_t)(n0 + lr) * ldb) * 2 + lbase;
    const uint32_t su   = (uint32_t)lr * 128 + lbase;
    const uint32_t sxor = (su >> 3) & 0x70;

    auto load_stage = [&](int s, int buf) {
        uint32_t ab = tiles_u + buf * STAGE_BYTES;
        uint32_t bb = ab + 16384;
        const char* a = gA + (size_t)s * 128;
        const char* b = gB + (size_t)s * 128;
#pragma unroll
        for (int i = 0; i < 4; i++) {
            uint32_t so = (su + i * 16) ^ sxor;
            cp16(ab + so, a + i * 16);
            cp16(bb + so, b + i * 16);
        }
        asm volatile("cp.async.commit_group;" ::: "memory");
    };

    load_stage(0, 0);
    load_stage(1, 1);

    const int lane = tid & 31, w = tid >> 5;
    const int wm = (w >> 2) * 64;
    const int wn = (w & 3) * 32;
    const int arow = lane & 15, ahalf = (lane >> 4) * 16;

    uint32_t pa[4], pb[2];
#pragma unroll
    for (int mf = 0; mf < 4; mf++)
        pa[mf] = swz128((uint32_t)((wm + mf * 16 + arow) * 128 + ahalf));
#pragma unroll
    for (int p = 0; p < 2; p++)
        pb[p] = swz128((uint32_t)((wn + p * 16 + arow) * 128 + ahalf));

    float acc[4][4][4];
#pragma unroll
    for (int mf = 0; mf < 4; mf++)
#pragma unroll
        for (int nf = 0; nf < 4; nf++)
#pragma unroll
            for (int i = 0; i < 4; i++) acc[mf][nf][i] = 0.f;

    int buf = 0, nbuf = 2;
    for (int s = 0; s < kchunks; s++) {
        asm volatile("cp.async.wait_group 1;" ::: "memory");
        __syncthreads();
        if (s + 2 < kchunks) load_stage(s + 2, nbuf);
        else asm volatile("cp.async.commit_group;" ::: "memory");

        uint32_t abase = tiles_u + buf * STAGE_BYTES;
        uint32_t bbase = abase + 16384;

        if (s < kchunks - 1) {
            COMPUTE_CHUNK(4);
        } else {
            COMPUTE_CHUNK(2);
        }
        buf = (buf == 2) ? 0 : buf + 1;
        nbuf = (nbuf == 2) ? 0 : nbuf + 1;
    }

    const int cg = lane >> 2;
    const int cc = (lane & 3) * 2;
#pragma unroll
    for (int mf = 0; mf < 4; mf++) {
        int r0 = m0 + wm + mf * 16 + cg;
        int r1 = r0 + 8;
#pragma unroll
        for (int nf = 0; nf < 4; nf++) {
            int col = wn + nf * 8 + cc;
            float b0 = sbias[col], b1v = sbias[col + 1];
            float v0 = acc[mf][nf][0] + b0, v1 = acc[mf][nf][1] + b1v;
            float v2 = acc[mf][nf][2] + b0, v3 = acc[mf][nf][3] + b1v;
            v0 = v0 > 0.f ? v0 : (__expf(v0) - 1.f);
            v1 = v1 > 0.f ? v1 : (__expf(v1) - 1.f);
            v2 = v2 > 0.f ? v2 : (__expf(v2) - 1.f);
            v3 = v3 > 0.f ? v3 : (__expf(v3) - 1.f);
            *(__nv_bfloat162*)(C + (size_t)r0 * ldc + n0 + col) = __floats2bfloat162_rn(v0, v1);
            *(__nv_bfloat162*)(C + (size_t)r1 * ldc + n0 + col) = __floats2bfloat162_rn(v2, v3);
        }
    }
}

// ---------------- para norm partial sums (reads para bf16 from h3 slot 8) ----------------
__global__ void paranorm_kernel(const __nv_bfloat16* __restrict__ p8, float* __restrict__ partial) {
    __shared__ float s[64];
    int tid = threadIdx.x;                    // 64 threads
    int row = blockIdx.x * 8 + (tid >> 3);
    int col = tid & 7;
    float v = __bfloat162float(p8[(size_t)row * M_OUT + col]);
    s[tid] = v * v;
    __syncthreads();
    for (int off = 32; off; off >>= 1) {
        if (tid < off) s[tid] += s[tid + off];
        __syncthreads();
    }
    if (tid == 0) partial[blockIdx.x] = s[0];
}

__global__ void reduce_norm_kernel(const float* __restrict__ partial, float* __restrict__ invnorm) {
    __shared__ float s[256];
    int tid = threadIdx.x;
    float v = 0.f;
    for (int k = 0; k < 8; k++) v += partial[tid + k * 256];
    s[tid] = v;
    __syncthreads();
    for (int off = 128; off; off >>= 1) {
        if (tid < off) s[tid] += s[tid + off];
        __syncthreads();
    }
    if (tid == 0) *invnorm = rsqrtf(s[0]);
}

// ---------------- combine: out = sigmoid(invnorm * sum_e para[b,e]*h3[e,b,m]) ----------------
__global__ void combine_kernel(const __nv_bfloat16* __restrict__ p8,
                               const __nv_bfloat16* __restrict__ h3,
                               const float* __restrict__ invnorm, float* __restrict__ out) {
    int t = blockIdx.x * 256 + threadIdx.x;
    int b = t >> 7;
    float inv = *invnorm;
    uint4 pv = *(const uint4*)(p8 + (size_t)b * M_OUT);   // 8 bf16
    const __nv_bfloat162* pp = (const __nv_bfloat162*)&pv;
    float acc = 0.f;
#pragma unroll
    for (int q = 0; q < 4; q++) {
        float2 pe = __bfloat1622float2(pp[q]);
        acc += pe.x * __bfloat162float(h3[(size_t)(2 * q)     * B_ * M_OUT + t]);
        acc += pe.y * __bfloat162float(h3[(size_t)(2 * q + 1) * B_ * M_OUT + t]);
    }
    float x = acc * inv;
    out[t] = 1.f / (1.f + __expf(-x));
}

// ---------------- host launcher ----------------
extern "C" void kernel_launch(void* const* d_in, const int* in_sizes, int n_in,
                              void* d_out, int out_size) {
    const float* motions = (const float*)d_in[0];
    const float* z       = (const float*)d_in[1];
    const float* gw1     = (const float*)d_in[2];
    const float* gb1     = (const float*)d_in[3];
    const float* gw2     = (const float*)d_in[4];
    const float* gb2     = (const float*)d_in[5];
    const float* gw3     = (const float*)d_in[6];
    const float* gb3     = (const float*)d_in[7];
    const float* W1      = (const float*)d_in[8];
    const float* b1      = (const float*)d_in[9];
    const float* W2      = (const float*)d_in[10];
    const float* b2      = (const float*)d_in[11];
    const float* W3      = (const float*)d_in[12];
    const float* b3      = (const float*)d_in[13];
    float* out = (float*)d_out;

    unsigned char* sc = nullptr;
    cudaGetSymbolAddress((void**)&sc, g_scratch);
    __nv_bfloat16* xpad = (__nv_bfloat16*)(sc + OFF_XPAD);
    __nv_bfloat16* h1e  = (__nv_bfloat16*)(sc + OFF_H1);
    __nv_bfloat16* h2e  = (__nv_bfloat16*)(sc + OFF_H2);
    __nv_bfloat16* h3   = (__nv_bfloat16*)(sc + OFF_H3);
    float* part = (float*)(sc + OFF_PART);
    float* inv  = (float*)(sc + OFF_INV);
    __nv_bfloat16* W1t  = (__nv_bfloat16*)(sc + OFF_W1T);
    __nv_bfloat16* W2t  = (__nv_bfloat16*)(sc + OFF_W2T);
    __nv_bfloat16* W3t  = (__nv_bfloat16*)(sc + OFF_W3T);
    float* b1a = (float*)(sc + OFF_B1A);
    float* b2a = (float*)(sc + OFF_B2A);
    float* b3a = (float*)(sc + OFF_B3A);
    __nv_bfloat16* para8 = h3 + (size_t)NE * B_ * M_OUT;   // h3 slot 8 = gate para

    cudaFuncSetAttribute(gemm_bias_elu, cudaFuncAttributeMaxDynamicSharedMemorySize, SMEM_BYTES);

    // one fused setup launch: prep + coalesced weight transposes (incl. gw3 pad) + biases
    setup_kernel<<<SEG4, 256>>>(motions, z, gw1, gw2, gw3, W1, W2, W3,
                                gb1, gb2, gb3, b1, b2, b3,
                                xpad, h1e, h2e, W1t, W2t, W3t, b1a, b2a, b3a);

    dim3 gL12(B_ / 128, 4, NS);   // 9 z-slices: experts 0..7 + gate
    dim3 gL3(B_ / 128, 1, NS);    // L3 also 9 slices: slice 8 = gate layer 3 (para)

    // Layer 1: out slot e of h1e (gate -> slot 8)
    gemm_bias_elu<<<gL12, 256, SMEM_BYTES>>>(xpad, KX, 0,
                                             W1t, KX, (size_t)H * KX,
                                             b1a, H,
                                             h1e, KH, (size_t)B_ * KH, KX / 64);
    // Layer 2
    gemm_bias_elu<<<gL12, 256, SMEM_BYTES>>>(h1e, KH, (size_t)B_ * KH,
                                             W2t, KH, (size_t)H * KH,
                                             b2a, H,
                                             h2e, KH, (size_t)B_ * KH, KH / 64);
    // Layer 3: experts + gate para in one launch
    gemm_bias_elu<<<gL3, 256, SMEM_BYTES>>>(h2e, KH, (size_t)B_ * KH,
                                            W3t, KH, (size_t)M_OUT * KH,
                                            b3a, M_OUT,
                                            h3, M_OUT, (size_t)B_ * M_OUT, KH / 64);

    // norm of para (deterministic partial sums -> single-block reduce)
    paranorm_kernel<<<2048, 64>>>(para8, part);
    reduce_norm_kernel<<<1, 256>>>(part, inv);

    combine_kernel<<<(B_ * M_OUT) / 256, 256>>>(para8, h3, inv, out);
}